// round 9
// baseline (speedup 1.0000x reference)
#include <cuda_runtime.h>
#include <cuda_bf16.h>
#include <cuda_fp16.h>
#include <cstdint>

// GraphSAGE: N=50000, E=800000, 128 -> 128 -> 128 -> 32
// FUSED layer kernels: [produce 64 rows (norm or aggregate) into smem as
// split bf16] -> [tensor-core GEMM] in ONE kernel. Split activations never
// touch global memory. 5 kernels on the critical path (was 9).
//  - 3-term bf16-split mma.sync m16n8k16 (fp32-grade accuracy ~5e-5).
//  - fp16 mirrors (q0/q1) for neighbor gathers; self terms fp32 (t0/t1).
//  - Bucket CSR (96 slots, Poisson(16) tail ~ 0), built concurrently.

#define NN 50000
#define FDIM 128
#define OUTF 32
#define CAP 96

typedef __nv_bfloat16 bf16;

__device__ bf16   g_wh[73728];
__device__ bf16   g_wl[73728];
__device__ float  g_t0[NN * FDIM];
__device__ float  g_t1[NN * FDIM];
__device__ __half g_q0[NN * FDIM];
__device__ __half g_q1[NN * FDIM];
__device__ int    g_cnt[NN];
__device__ int    g_col[NN * CAP];
__device__ int    g_is64;

// ---------------------------------------------------------------------------
__device__ __forceinline__ void split_bf16(float v, bf16& hi, bf16& lo) {
    hi = __float2bfloat16_rn(v);
    lo = __float2bfloat16_rn(v - __bfloat162float(hi));
}

__device__ __forceinline__ void cpa16(uint32_t dst, const void* src, int szz) {
    asm volatile("cp.async.ca.shared.global [%0], [%1], 16, %2;"
                 :: "r"(dst), "l"(src), "r"(szz));
}
#define CP_COMMIT asm volatile("cp.async.commit_group;" ::: "memory")
#define CP_WAIT1  asm volatile("cp.async.wait_group 1;" ::: "memory")
#define CP_WAIT0  asm volatile("cp.async.wait_group 0;" ::: "memory")

__device__ __forceinline__ void ldsm4(uint32_t r[4], uint32_t addr) {
    asm volatile("ldmatrix.sync.aligned.m8n8.x4.shared.b16 {%0,%1,%2,%3}, [%4];"
                 : "=r"(r[0]), "=r"(r[1]), "=r"(r[2]), "=r"(r[3]) : "r"(addr));
}
__device__ __forceinline__ void ldsm4t(uint32_t r[4], uint32_t addr) {
    asm volatile("ldmatrix.sync.aligned.m8n8.x4.trans.shared.b16 {%0,%1,%2,%3}, [%4];"
                 : "=r"(r[0]), "=r"(r[1]), "=r"(r[2]), "=r"(r[3]) : "r"(addr));
}
__device__ __forceinline__ void mma16816(float d[4], const uint32_t a[4],
                                         const uint32_t* b) {
    asm volatile(
        "mma.sync.aligned.m16n8k16.row.col.f32.bf16.bf16.f32 "
        "{%0,%1,%2,%3}, {%4,%5,%6,%7}, {%8,%9}, {%0,%1,%2,%3};"
        : "+f"(d[0]), "+f"(d[1]), "+f"(d[2]), "+f"(d[3])
        : "r"(a[0]), "r"(a[1]), "r"(a[2]), "r"(a[3]), "r"(b[0]), "r"(b[1]));
}

// ---------------------------------------------------------------------------
__device__ __forceinline__ int eidx(const void* p, int i, int is64) {
    return is64 ? (int)((const long long*)p)[i] : ((const int*)p)[i];
}

__global__ void k_zero_detect(const int* w, int n, int e) {
    for (int i = blockIdx.x * blockDim.x + threadIdx.x; i < e;
         i += gridDim.x * blockDim.x) {
        if (i < n) g_cnt[i] = 0;
        if ((i & 1) && w[i] != 0) g_is64 = 0;
    }
}

__global__ void k_scatter(const void* src, const void* dst, int e) {
    int is64 = g_is64;
    for (int i = blockIdx.x * blockDim.x + threadIdx.x; i < e;
         i += gridDim.x * blockDim.x) {
        int d = eidx(dst, i, is64);
        int p = atomicAdd(&g_cnt[d], 1);
        if (p < CAP) g_col[d * CAP + p] = eidx(src, i, is64);
    }
}

// ---------------------------------------------------------------------------
// Weight pre-split. Layout ([k][m] row-major regions):
//  [0, 32768)      : cat(Wself0 | Wneigh0)  [128][256]
//  [32768, 49152)  : Wneigh1               [128][128]
//  [49152, 65536)  : Wneigh2               [128][128]
//  [65536, 73728)  : cat(Wself3 | Wneigh3) [128][64]
// ---------------------------------------------------------------------------
__global__ void k_wsplit(const float* __restrict__ ws0, const float* __restrict__ wn0,
                         const float* __restrict__ wn1, const float* __restrict__ wn2,
                         const float* __restrict__ ws3, const float* __restrict__ wn3) {
    int i = blockIdx.x * blockDim.x + threadIdx.x;
    if (i >= 73728) return;
    float v;
    if (i < 32768) {
        int r = i >> 8, m = i & 255;
        v = (m < 128) ? ws0[r * 128 + m] : wn0[r * 128 + m - 128];
    } else if (i < 49152) v = wn1[i - 32768];
    else if (i < 65536)   v = wn2[i - 49152];
    else {
        int j = i - 65536, r = j >> 6, c = j & 63;
        v = (c < 32) ? ws3[r * 32 + c] : wn3[r * 32 + c - 32];
    }
    bf16 hi, lo;
    split_bf16(v, hi, lo);
    g_wh[i] = hi;
    g_wl[i] = lo;
}

// ---------------------------------------------------------------------------
// gather helpers
// ---------------------------------------------------------------------------
__device__ __forceinline__ float4 h4_to_f4(uint2 raw) {
    __half2 p0 = *(__half2*)&raw.x;
    __half2 p1 = *(__half2*)&raw.y;
    float2 f0 = __half22float2(p0), f1 = __half22float2(p1);
    return make_float4(f0.x, f0.y, f1.x, f1.y);
}
__device__ __forceinline__ void acc4(float4& a, float4 t) {
    a.x += t.x; a.y += t.y; a.z += t.z; a.w += t.w;
}

__device__ __forceinline__ float4 gather_sum(const __half* __restrict__ q,
                                             int v, int lane, int& dt) {
    dt = g_cnt[v];
    int L = dt < CAP ? dt : CAP;
    const int* cp = g_col + v * CAP;
    float4 acc = make_float4(0.f, 0.f, 0.f, 0.f);
    int j = 0;
    for (; j + 4 <= L; j += 4) {
        int4 u = *(const int4*)(cp + j);
        uint2 a0 = *(const uint2*)(q + (size_t)u.x * FDIM + lane * 4);
        uint2 a1 = *(const uint2*)(q + (size_t)u.y * FDIM + lane * 4);
        uint2 a2 = *(const uint2*)(q + (size_t)u.z * FDIM + lane * 4);
        uint2 a3 = *(const uint2*)(q + (size_t)u.w * FDIM + lane * 4);
        acc4(acc, h4_to_f4(a0)); acc4(acc, h4_to_f4(a1));
        acc4(acc, h4_to_f4(a2)); acc4(acc, h4_to_f4(a3));
    }
    for (; j < L; j++) {
        int u = cp[j];
        acc4(acc, h4_to_f4(*(const uint2*)(q + (size_t)u * FDIM + lane * 4)));
    }
    return acc;
}

// ---------------------------------------------------------------------------
// W chunk staging into smem (16 k-rows, padded LDB = M+8)
// ---------------------------------------------------------------------------
template <int M>
__device__ __forceinline__ void stage_w(uint32_t dWh, uint32_t dWl,
                                        const bf16* __restrict__ Wgh,
                                        const bf16* __restrict__ Wgl,
                                        int k0, int tid) {
    constexpr int CW = M / 8, LDB = M + 8;
    #pragma unroll
    for (int i = tid; i < 2 * 16 * CW; i += 256) {
        int half = i / (16 * CW), rem = i % (16 * CW);
        int r = rem / CW, seg = rem % CW;
        size_t so = (size_t)(k0 + r) * M + seg * 8;
        uint32_t dof = (uint32_t)(r * LDB + seg * 8) * 2;
        if (half == 0) cpa16(dWh + dof, Wgh + so, 16);
        else           cpa16(dWl + dof, Wgl + so, 16);
    }
}

// ---------------------------------------------------------------------------
// FUSED kernel: produce 64 rows (MODE 0=norm, 1=mean-agg, 2=gcn-agg) into
// smem split-bf16, then GEMM vs [128, M] weights.
// Epilogue: M=256 -> cols[0:128) fp32 C, [128:256) fp16 Q;
//           M=128 -> fp32 C + fp16 Q;   M=64 -> fp32 C only.
// ---------------------------------------------------------------------------
template <int MODE, int M>
__global__ void __launch_bounds__(256) k_fused(
    const float* __restrict__ X,       // x (MODE0) or fp32 self-term buffer
    const __half* __restrict__ Qin,    // fp16 neighbor mirror (agg modes)
    const float* __restrict__ bias,    // layer bias (agg modes)
    const bf16* __restrict__ Wgh, const bf16* __restrict__ Wgl,
    float* __restrict__ C, __half* __restrict__ Qout, int n) {
    constexpr int LDA = 136;                  // bf16; 272B rows, ldsm-safe
    constexpr int ABYTES = 64 * LDA * 2;      // 17408
    constexpr int LDB = M + 8;
    constexpr int WBUF = 16 * LDB * 2;
    constexpr int NT = M / 32;                // n-tiles per warp (2 warp groups)

    extern __shared__ char sm[];
    uint32_t sA  = (uint32_t)__cvta_generic_to_shared(sm);
    uint32_t sAh = sA, sAl = sA + ABYTES;
    uint32_t sWh[2] = {sA + 2 * ABYTES, sA + 2 * ABYTES + WBUF};
    uint32_t sWl[2] = {sA + 2 * ABYTES + 2 * WBUF, sA + 2 * ABYTES + 3 * WBUF};
    bf16* Ah = (bf16*)sm;
    bf16* Al = (bf16*)(sm + ABYTES);

    int tid = threadIdx.x, lane = tid & 31, wid = tid >> 5;
    int row0 = blockIdx.x * 64;

    // prefetch W chunk 0 (overlaps with the produce phase below)
    stage_w<M>(sWh[0], sWl[0], Wgh, Wgl, 0, tid);
    CP_COMMIT;

    // ---- phase A: produce 8 rows per warp ----
    #pragma unroll 1
    for (int i = 0; i < 8; i++) {
        int lr = wid * 8 + i;
        int v = row0 + lr;
        float4 o = make_float4(0.f, 0.f, 0.f, 0.f);
        if (v < n) {
            if (MODE == 0) {
                float4 a = *(const float4*)(X + (size_t)v * FDIM + lane * 4);
                float ss = a.x * a.x + a.y * a.y + a.z * a.z + a.w * a.w;
                #pragma unroll
                for (int off = 16; off; off >>= 1)
                    ss += __shfl_xor_sync(0xFFFFFFFFu, ss, off);
                float s = 1.0f / fmaxf(sqrtf(ss), 1e-12f);
                o = make_float4(a.x * s, a.y * s, a.z * s, a.w * s);
            } else {
                int dt;
                float4 acc = gather_sum(Qin, v, lane, dt);
                float4 sf = *(const float4*)(X + (size_t)v * FDIM + lane * 4);
                float4 bb = *(const float4*)(bias + lane * 4);
                if (MODE == 1) {
                    float inv = 1.0f / fmaxf((float)dt, 1.0f);
                    o.x = fmaxf(sf.x + acc.x * inv + bb.x, 0.f);
                    o.y = fmaxf(sf.y + acc.y * inv + bb.y, 0.f);
                    o.z = fmaxf(sf.z + acc.z * inv + bb.z, 0.f);
                    o.w = fmaxf(sf.w + acc.w * inv + bb.w, 0.f);
                } else {
                    acc4(acc, sf);
                    float inv = 1.0f / ((float)dt + 1.0f);
                    o.x = fmaxf(acc.x * inv + bb.x, 0.f);
                    o.y = fmaxf(acc.y * inv + bb.y, 0.f);
                    o.z = fmaxf(acc.z * inv + bb.z, 0.f);
                    o.w = fmaxf(acc.w * inv + bb.w, 0.f);
                }
            }
        }
        int off = lr * LDA + lane * 4;
        bf16 h0, l0, h1, l1, h2, l2, h3, l3;
        split_bf16(o.x, h0, l0); split_bf16(o.y, h1, l1);
        split_bf16(o.z, h2, l2); split_bf16(o.w, h3, l3);
        *(__nv_bfloat162*)(Ah + off)     = __nv_bfloat162(h0, h1);
        *(__nv_bfloat162*)(Ah + off + 2) = __nv_bfloat162(h2, h3);
        *(__nv_bfloat162*)(Al + off)     = __nv_bfloat162(l0, l1);
        *(__nv_bfloat162*)(Al + off + 2) = __nv_bfloat162(l2, l3);
    }
    __syncthreads();

    // ---- phase B: GEMM, K=128 in 8 chunks of 16 ----
    float acc[NT][2][4];
    #pragma unroll
    for (int t = 0; t < NT; t++)
        #pragma unroll
        for (int s = 0; s < 2; s++)
            #pragma unroll
            for (int c = 0; c < 4; c++) acc[t][s][c] = 0.f;

    int mtile = wid & 3, ng = wid >> 2;

    #pragma unroll
    for (int c = 0; c < 8; c++) {
        int b = c & 1;
        if (c < 7) {
            stage_w<M>(sWh[(c + 1) & 1], sWl[(c + 1) & 1], Wgh, Wgl,
                       (c + 1) * 16, tid);
            CP_COMMIT;
            CP_WAIT1;
        } else {
            CP_WAIT0;
        }
        __syncthreads();

        uint32_t aoff =
            ((mtile * 16 + (lane & 15)) * LDA + c * 16 + (lane >> 4) * 8) * 2;
        uint32_t ah[4], al[4];
        ldsm4(ah, sAh + aoff);
        ldsm4(al, sAl + aoff);
        #pragma unroll
        for (int nt = 0; nt < NT; nt++) {
            int ncol = ng * (M / 2) + nt * 16;
            uint32_t boff = ((lane & 15) * LDB + ncol + (lane >> 4) * 8) * 2;
            uint32_t bh[4], bl[4];
            ldsm4t(bh, sWh[b] + boff);
            ldsm4t(bl, sWl[b] + boff);
            mma16816(acc[nt][0], ah, bh + 0);
            mma16816(acc[nt][1], ah, bh + 2);
            mma16816(acc[nt][0], al, bh + 0);
            mma16816(acc[nt][1], al, bh + 2);
            mma16816(acc[nt][0], ah, bl + 0);
            mma16816(acc[nt][1], ah, bl + 2);
        }
        __syncthreads();
    }

    // ---- epilogue ----
    int g = lane >> 2, tg = lane & 3;
    int r0 = row0 + mtile * 16 + g;
    #pragma unroll
    for (int nt = 0; nt < NT; nt++) {
        #pragma unroll
        for (int s = 0; s < 2; s++) {
            int coln = ng * (M / 2) + nt * 16 + s * 8 + tg * 2;
            float2 v01 = make_float2(acc[nt][s][0], acc[nt][s][1]);
            float2 v23 = make_float2(acc[nt][s][2], acc[nt][s][3]);
            if (M == 256) {
                if (ng == 0) {
                    if (r0 < n)     *(float2*)(C + (size_t)r0 * 128 + coln) = v01;
                    if (r0 + 8 < n) *(float2*)(C + (size_t)(r0 + 8) * 128 + coln) = v23;
                } else {
                    int qc = coln - 128;
                    if (r0 < n)     *(__half2*)(Qout + (size_t)r0 * 128 + qc) =
                        __float22half2_rn(v01);
                    if (r0 + 8 < n) *(__half2*)(Qout + (size_t)(r0 + 8) * 128 + qc) =
                        __float22half2_rn(v23);
                }
            } else if (M == 128) {
                if (r0 < n) {
                    *(float2*)(C + (size_t)r0 * 128 + coln) = v01;
                    *(__half2*)(Qout + (size_t)r0 * 128 + coln) =
                        __float22half2_rn(v01);
                }
                if (r0 + 8 < n) {
                    *(float2*)(C + (size_t)(r0 + 8) * 128 + coln) = v23;
                    *(__half2*)(Qout + (size_t)(r0 + 8) * 128 + coln) =
                        __float22half2_rn(v23);
                }
            } else {  // M == 64: fp32 only
                if (r0 < n)     *(float2*)(C + (size_t)r0 * 64 + coln) = v01;
                if (r0 + 8 < n) *(float2*)(C + (size_t)(r0 + 8) * 64 + coln) = v23;
            }
        }
    }
}

// ---------------------------------------------------------------------------
// Final aggregation (layer 3, fp32, 32-dim): t is [n,64] = self|neigh
// ---------------------------------------------------------------------------
__global__ void k_agg_mean32(const float* __restrict__ t,
                             const float* __restrict__ b,
                             float* __restrict__ out, int n) {
    int v = (blockIdx.x * blockDim.x + threadIdx.x) >> 5;
    int lane = threadIdx.x & 31;
    if (v >= n) return;
    int dt = g_cnt[v];
    int L = dt < CAP ? dt : CAP;
    const int* cp = g_col + v * CAP;
    float acc = 0.f;
    int j = 0;
    for (; j + 4 <= L; j += 4) {
        int4 u = *(const int4*)(cp + j);
        float a0 = t[(size_t)u.x * 64 + 32 + lane];
        float a1 = t[(size_t)u.y * 64 + 32 + lane];
        float a2 = t[(size_t)u.z * 64 + 32 + lane];
        float a3 = t[(size_t)u.w * 64 + 32 + lane];
        acc += a0 + a1 + a2 + a3;
    }
    for (; j < L; j++) acc += t[(size_t)cp[j] * 64 + 32 + lane];
    float inv = 1.0f / fmaxf((float)dt, 1.0f);
    out[(size_t)v * OUTF + lane] = t[(size_t)v * 64 + lane] + acc * inv + b[lane];
}

// ---------------------------------------------------------------------------
extern "C" void kernel_launch(void* const* d_in, const int* in_sizes, int n_in,
                              void* d_out, int out_size) {
    const float* x       = (const float*)d_in[0];
    const void*  src     = d_in[1];
    const void*  dst     = d_in[2];
    const float* Wself0  = (const float*)d_in[3];
    const float* Wneigh0 = (const float*)d_in[4];
    const float* b0      = (const float*)d_in[5];
    const float* Wneigh1 = (const float*)d_in[6];
    const float* b1      = (const float*)d_in[7];
    const float* Wneigh2 = (const float*)d_in[8];
    const float* b2      = (const float*)d_in[9];
    const float* Wself3  = (const float*)d_in[10];
    const float* Wneigh3 = (const float*)d_in[11];
    const float* b3      = (const float*)d_in[12];
    float* out = (float*)d_out;

    int n = in_sizes[0] / FDIM;
    int e = in_sizes[1];

    bf16 *wh, *wl;
    float *t0, *t1;
    __half *q0, *q1;
    int* is64p;
    cudaGetSymbolAddress((void**)&wh, g_wh);
    cudaGetSymbolAddress((void**)&wl, g_wl);
    cudaGetSymbolAddress((void**)&t0, g_t0);
    cudaGetSymbolAddress((void**)&t1, g_t1);
    cudaGetSymbolAddress((void**)&q0, g_q0);
    cudaGetSymbolAddress((void**)&q1, g_q1);
    cudaGetSymbolAddress((void**)&is64p, g_is64);

    constexpr int SM_F0 = 2 * 17408 + 4 * (16 * 264 * 2);  // 68608
    constexpr int SM_FM = 2 * 17408 + 4 * (16 * 136 * 2);  // 52224
    constexpr int SM_F3 = 2 * 17408 + 4 * (16 * 72 * 2);   // 44032

    static cudaStream_t s1 = nullptr, s2 = nullptr;
    static cudaEvent_t eFork = nullptr, eCSR = nullptr, eW = nullptr;
    if (!s1) {
        cudaStreamCreateWithFlags(&s1, cudaStreamNonBlocking);
        cudaStreamCreateWithFlags(&s2, cudaStreamNonBlocking);
        cudaEventCreateWithFlags(&eFork, cudaEventDisableTiming);
        cudaEventCreateWithFlags(&eCSR,  cudaEventDisableTiming);
        cudaEventCreateWithFlags(&eW,    cudaEventDisableTiming);
        cudaFuncSetAttribute(k_fused<0, 256>,
                             cudaFuncAttributeMaxDynamicSharedMemorySize, SM_F0);
        cudaFuncSetAttribute(k_fused<1, 128>,
                             cudaFuncAttributeMaxDynamicSharedMemorySize, SM_FM);
        cudaFuncSetAttribute(k_fused<2, 128>,
                             cudaFuncAttributeMaxDynamicSharedMemorySize, SM_FM);
        cudaFuncSetAttribute(k_fused<2, 64>,
                             cudaFuncAttributeMaxDynamicSharedMemorySize, SM_F3);
    }

    int fb = (n + 63) / 64;
    int aggBlocks = (n + 7) / 8;

    // fork: CSR build (s1) and weight split (s2) off the main chain
    cudaMemsetAsync(is64p, 1, 4);               // nonzero => int64 until refuted
    cudaEventRecord(eFork, 0);

    cudaStreamWaitEvent(s1, eFork, 0);
    k_zero_detect<<<1024, 256, 0, s1>>>((const int*)dst, n, e);
    k_scatter<<<1024, 256, 0, s1>>>(src, dst, e);
    cudaEventRecord(eCSR, s1);

    cudaStreamWaitEvent(s2, eFork, 0);
    k_wsplit<<<(73728 + 255) / 256, 256, 0, s2>>>(Wself0, Wneigh0, Wneigh1,
                                                  Wneigh2, Wself3, Wneigh3);
    cudaEventRecord(eW, s2);

    // F0: norm + dual GEMM0 -> t0 (self fp32), q0 (neigh fp16)
    cudaStreamWaitEvent(0, eW, 0);
    k_fused<0, 256><<<fb, 256, SM_F0>>>(x, q0, b0, wh, wl, t0, q0, n);

    // F1: mean-agg(t0,q0,b0) + GEMM(Wneigh1) -> t1, q1
    cudaStreamWaitEvent(0, eCSR, 0);
    k_fused<1, 128><<<fb, 256, SM_FM>>>(t0, q0, b0, wh + 32768, wl + 32768,
                                        t1, q1, n);

    // F2: gcn-agg(t1,q1,b1) + GEMM(Wneigh2) -> t0, q0
    k_fused<2, 128><<<fb, 256, SM_FM>>>(t1, q1, b1, wh + 49152, wl + 49152,
                                        t0, q0, n);

    // F3: gcn-agg(t0,q0,b2) + GEMM(Wself3|Wneigh3) -> t1 [n][64] fp32
    k_fused<2, 64><<<fb, 256, SM_F3>>>(t0, q0, b2, wh + 65536, wl + 65536,
                                       t1, q1, n);

    // final mean aggregation (32-dim) -> out
    k_agg_mean32<<<aggBlocks, 256>>>(t1, b3, out, n);
}

// round 10
// speedup vs baseline: 1.1588x; 1.1588x over previous
#include <cuda_runtime.h>
#include <cuda_bf16.h>
#include <cuda_fp16.h>
#include <cstdint>

// GraphSAGE: N=50000, E=800000, 128 -> 128 -> 128 -> 32
// R8 structure (separate agg/GEMM kernels + fork-join streams) with dead
// fp32 traffic removed:
//  - L0-neigh / L1 / L2 GEMMs write ONLY the fp16 mirror q (fp32 C unused).
//  - gcn aggs read self from q (fp16) too; mean-agg self stays fp32 (t0).
//  - Activations PRE-SPLIT bf16 hi/lo for 3-term tensor-core GEMM.
//  - Bucket CSR (96 slots), built concurrently on a side stream.

#define NN 50000
#define FDIM 128
#define OUTF 32
#define CAP 96

typedef __nv_bfloat16 bf16;

__device__ bf16   g_ah[NN * FDIM];
__device__ bf16   g_al[NN * FDIM];
__device__ bf16   g_wh[73728];
__device__ bf16   g_wl[73728];
__device__ float  g_t0[NN * FDIM];
__device__ __half g_q [NN * FDIM];
__device__ int    g_cnt[NN];
__device__ int    g_col[NN * CAP];
__device__ int    g_is64;

// ---------------------------------------------------------------------------
__device__ __forceinline__ void split_bf16(float v, bf16& hi, bf16& lo) {
    hi = __float2bfloat16_rn(v);
    lo = __float2bfloat16_rn(v - __bfloat162float(hi));
}

__device__ __forceinline__ void store_split4(size_t off, float4 o) {
    bf16 h0, l0, h1, l1, h2, l2, h3, l3;
    split_bf16(o.x, h0, l0); split_bf16(o.y, h1, l1);
    split_bf16(o.z, h2, l2); split_bf16(o.w, h3, l3);
    *(__nv_bfloat162*)(g_ah + off)     = __nv_bfloat162(h0, h1);
    *(__nv_bfloat162*)(g_ah + off + 2) = __nv_bfloat162(h2, h3);
    *(__nv_bfloat162*)(g_al + off)     = __nv_bfloat162(l0, l1);
    *(__nv_bfloat162*)(g_al + off + 2) = __nv_bfloat162(l2, l3);
}

__device__ __forceinline__ void cpa16(uint32_t dst, const void* src, int szz) {
    asm volatile("cp.async.ca.shared.global [%0], [%1], 16, %2;"
                 :: "r"(dst), "l"(src), "r"(szz));
}
#define CP_COMMIT asm volatile("cp.async.commit_group;" ::: "memory")
#define CP_WAIT1  asm volatile("cp.async.wait_group 1;" ::: "memory")
#define CP_WAIT0  asm volatile("cp.async.wait_group 0;" ::: "memory")

__device__ __forceinline__ void ldsm4(uint32_t r[4], uint32_t addr) {
    asm volatile("ldmatrix.sync.aligned.m8n8.x4.shared.b16 {%0,%1,%2,%3}, [%4];"
                 : "=r"(r[0]), "=r"(r[1]), "=r"(r[2]), "=r"(r[3]) : "r"(addr));
}
__device__ __forceinline__ void ldsm4t(uint32_t r[4], uint32_t addr) {
    asm volatile("ldmatrix.sync.aligned.m8n8.x4.trans.shared.b16 {%0,%1,%2,%3}, [%4];"
                 : "=r"(r[0]), "=r"(r[1]), "=r"(r[2]), "=r"(r[3]) : "r"(addr));
}
__device__ __forceinline__ void mma16816(float d[4], const uint32_t a[4],
                                         const uint32_t* b) {
    asm volatile(
        "mma.sync.aligned.m16n8k16.row.col.f32.bf16.bf16.f32 "
        "{%0,%1,%2,%3}, {%4,%5,%6,%7}, {%8,%9}, {%0,%1,%2,%3};"
        : "+f"(d[0]), "+f"(d[1]), "+f"(d[2]), "+f"(d[3])
        : "r"(a[0]), "r"(a[1]), "r"(a[2]), "r"(a[3]), "r"(b[0]), "r"(b[1]));
}

// ---------------------------------------------------------------------------
__device__ __forceinline__ int eidx(const void* p, int i, int is64) {
    return is64 ? (int)((const long long*)p)[i] : ((const int*)p)[i];
}

__global__ void k_zero_detect(const int* w, int n, int e) {
    for (int i = blockIdx.x * blockDim.x + threadIdx.x; i < e;
         i += gridDim.x * blockDim.x) {
        if (i < n) g_cnt[i] = 0;
        if ((i & 1) && w[i] != 0) g_is64 = 0;
    }
}

__global__ void k_scatter(const void* src, const void* dst, int e) {
    int is64 = g_is64;
    for (int i = blockIdx.x * blockDim.x + threadIdx.x; i < e;
         i += gridDim.x * blockDim.x) {
        int d = eidx(dst, i, is64);
        int p = atomicAdd(&g_cnt[d], 1);
        if (p < CAP) g_col[d * CAP + p] = eidx(src, i, is64);
    }
}

// ---------------------------------------------------------------------------
// Weight pre-split: [0)=Wself0 [16384)=Wneigh0 [32768)=Wneigh1 [49152)=Wneigh2
// [65536, 73728) = concat(Wself3 | Wneigh3) as [128 x 64]
// ---------------------------------------------------------------------------
__global__ void k_wsplit(const float* __restrict__ ws0, const float* __restrict__ wn0,
                         const float* __restrict__ wn1, const float* __restrict__ wn2,
                         const float* __restrict__ ws3, const float* __restrict__ wn3) {
    int i = blockIdx.x * blockDim.x + threadIdx.x;
    if (i >= 73728) return;
    float v;
    if (i < 16384) v = ws0[i];
    else if (i < 32768) v = wn0[i - 16384];
    else if (i < 49152) v = wn1[i - 32768];
    else if (i < 65536) v = wn2[i - 49152];
    else {
        int j = i - 65536, r = j >> 6, c = j & 63;
        v = (c < 32) ? ws3[r * 32 + c] : wn3[r * 32 + c - 32];
    }
    bf16 hi, lo;
    split_bf16(v, hi, lo);
    g_wh[i] = hi;
    g_wl[i] = lo;
}

// ---------------------------------------------------------------------------
__global__ void k_norm(const float* __restrict__ x, int n) {
    int v = (blockIdx.x * blockDim.x + threadIdx.x) >> 5;
    int lane = threadIdx.x & 31;
    if (v >= n) return;
    float4 a = *(const float4*)(x + (size_t)v * FDIM + lane * 4);
    float ss = a.x * a.x + a.y * a.y + a.z * a.z + a.w * a.w;
    #pragma unroll
    for (int o = 16; o; o >>= 1) ss += __shfl_xor_sync(0xFFFFFFFFu, ss, o);
    float s = 1.0f / fmaxf(sqrtf(ss), 1e-12f);
    a.x *= s; a.y *= s; a.z *= s; a.w *= s;
    store_split4((size_t)v * FDIM + lane * 4, a);
}

// ---------------------------------------------------------------------------
// Tensor GEMM: (Ah+Al)[n,128] @ (Wh+Wl)[128,M], 3-term split.
// QONLY=false: write fp32 C.  QONLY=true: write fp16 Q only.
// ---------------------------------------------------------------------------
template <int M>
__device__ __forceinline__ void stage_chunk(
    uint32_t dAh, uint32_t dAl, uint32_t dWh, uint32_t dWl,
    const bf16* __restrict__ Agh, const bf16* __restrict__ Agl,
    const bf16* __restrict__ Wgh, const bf16* __restrict__ Wgl,
    int row0, int k0, int n, int tid) {
    #pragma unroll
    for (int i = tid; i < 512; i += 256) {
        int rem = i & 255, r = rem >> 1, seg = rem & 1;
        int row = row0 + r;
        int ok = (row < n) ? 16 : 0;
        size_t so = (size_t)(ok ? row : 0) * 128 + k0 + seg * 8;
        uint32_t dof = (uint32_t)(r * 24 + seg * 8) * 2;
        if (i < 256) cpa16(dAh + dof, Agh + so, ok);
        else         cpa16(dAl + dof, Agl + so, ok);
    }
    constexpr int CW = M / 8;
    #pragma unroll
    for (int i = tid; i < 2 * 16 * CW; i += 256) {
        int half = i / (16 * CW), rem = i % (16 * CW);
        int r = rem / CW, seg = rem % CW;
        size_t so = (size_t)(k0 + r) * M + seg * 8;
        uint32_t dof = (uint32_t)(r * (M + 8) + seg * 8) * 2;
        if (half == 0) cpa16(dWh + dof, Wgh + so, 16);
        else           cpa16(dWl + dof, Wgl + so, 16);
    }
}

template <int M, bool QONLY>
__global__ void __launch_bounds__(256) k_gemm_bf(
    const bf16* __restrict__ Agh, const bf16* __restrict__ Agl,
    const bf16* __restrict__ Wgh, const bf16* __restrict__ Wgl,
    float* __restrict__ C, __half* __restrict__ Q, int n) {
    constexpr int LDA = 24;
    constexpr int LDB = M + 8;
    constexpr int NT  = M / 16;
    __shared__ bf16 Ah[2][128 * LDA], Al[2][128 * LDA];
    __shared__ bf16 Wh[2][16 * LDB], Wl[2][16 * LDB];

    int tid = threadIdx.x;
    int lane = tid & 31, wid = tid >> 5;
    int row0 = blockIdx.x * 128;

    float acc[NT][2][4];
    #pragma unroll
    for (int t = 0; t < NT; t++)
        #pragma unroll
        for (int s = 0; s < 2; s++)
            #pragma unroll
            for (int c = 0; c < 4; c++) acc[t][s][c] = 0.f;

    uint32_t sAh[2] = {(uint32_t)__cvta_generic_to_shared(Ah[0]),
                       (uint32_t)__cvta_generic_to_shared(Ah[1])};
    uint32_t sAl[2] = {(uint32_t)__cvta_generic_to_shared(Al[0]),
                       (uint32_t)__cvta_generic_to_shared(Al[1])};
    uint32_t sWh[2] = {(uint32_t)__cvta_generic_to_shared(Wh[0]),
                       (uint32_t)__cvta_generic_to_shared(Wh[1])};
    uint32_t sWl[2] = {(uint32_t)__cvta_generic_to_shared(Wl[0]),
                       (uint32_t)__cvta_generic_to_shared(Wl[1])};

    stage_chunk<M>(sAh[0], sAl[0], sWh[0], sWl[0], Agh, Agl, Wgh, Wgl,
                   row0, 0, n, tid);
    CP_COMMIT;

    #pragma unroll
    for (int c = 0; c < 8; c++) {
        int b = c & 1;
        if (c < 7) {
            int nb = (c + 1) & 1;
            stage_chunk<M>(sAh[nb], sAl[nb], sWh[nb], sWl[nb], Agh, Agl,
                           Wgh, Wgl, row0, (c + 1) * 16, n, tid);
            CP_COMMIT;
            CP_WAIT1;
        } else {
            CP_WAIT0;
        }
        __syncthreads();

        uint32_t aoff = ((wid * 16 + (lane & 15)) * LDA + (lane >> 4) * 8) * 2;
        uint32_t ah[4], al[4];
        ldsm4(ah, sAh[b] + aoff);
        ldsm4(al, sAl[b] + aoff);
        #pragma unroll
        for (int nt = 0; nt < NT; nt++) {
            uint32_t boff = ((lane & 15) * LDB + nt * 16 + (lane >> 4) * 8) * 2;
            uint32_t bh[4], bl[4];
            ldsm4t(bh, sWh[b] + boff);
            ldsm4t(bl, sWl[b] + boff);
            mma16816(acc[nt][0], ah, bh + 0);
            mma16816(acc[nt][1], ah, bh + 2);
            mma16816(acc[nt][0], al, bh + 0);
            mma16816(acc[nt][1], al, bh + 2);
            mma16816(acc[nt][0], ah, bl + 0);
            mma16816(acc[nt][1], ah, bl + 2);
        }
        __syncthreads();
    }

    int g = lane >> 2, tg = lane & 3;
    int r0 = row0 + wid * 16 + g;
    #pragma unroll
    for (int nt = 0; nt < NT; nt++) {
        #pragma unroll
        for (int s = 0; s < 2; s++) {
            int col = nt * 16 + s * 8 + tg * 2;
            float2 v01 = make_float2(acc[nt][s][0], acc[nt][s][1]);
            float2 v23 = make_float2(acc[nt][s][2], acc[nt][s][3]);
            if (QONLY) {
                if (r0 < n)
                    *(__half2*)(Q + (size_t)r0 * M + col) = __float22half2_rn(v01);
                if (r0 + 8 < n)
                    *(__half2*)(Q + (size_t)(r0 + 8) * M + col) =
                        __float22half2_rn(v23);
            } else {
                if (r0 < n)
                    *(float2*)(C + (size_t)r0 * M + col) = v01;
                if (r0 + 8 < n)
                    *(float2*)(C + (size_t)(r0 + 8) * M + col) = v23;
            }
        }
    }
}

// ---------------------------------------------------------------------------
// Aggregations: warp per node, bucket CSR, unroll-4 gathers.
// ---------------------------------------------------------------------------
__device__ __forceinline__ float4 h4_to_f4(uint2 raw) {
    __half2 p0 = *(__half2*)&raw.x;
    __half2 p1 = *(__half2*)&raw.y;
    float2 f0 = __half22float2(p0), f1 = __half22float2(p1);
    return make_float4(f0.x, f0.y, f1.x, f1.y);
}
__device__ __forceinline__ void acc4(float4& a, float4 t) {
    a.x += t.x; a.y += t.y; a.z += t.z; a.w += t.w;
}

__device__ __forceinline__ float4 gather_sum(const __half* __restrict__ q,
                                             int v, int lane, int& dt) {
    dt = g_cnt[v];
    int L = dt < CAP ? dt : CAP;
    const int* cp = g_col + v * CAP;
    float4 acc = make_float4(0.f, 0.f, 0.f, 0.f);
    int j = 0;
    for (; j + 4 <= L; j += 4) {
        int4 u = *(const int4*)(cp + j);
        uint2 a0 = *(const uint2*)(q + (size_t)u.x * FDIM + lane * 4);
        uint2 a1 = *(const uint2*)(q + (size_t)u.y * FDIM + lane * 4);
        uint2 a2 = *(const uint2*)(q + (size_t)u.z * FDIM + lane * 4);
        uint2 a3 = *(const uint2*)(q + (size_t)u.w * FDIM + lane * 4);
        acc4(acc, h4_to_f4(a0)); acc4(acc, h4_to_f4(a1));
        acc4(acc, h4_to_f4(a2)); acc4(acc, h4_to_f4(a3));
    }
    for (; j < L; j++) {
        int u = cp[j];
        acc4(acc, h4_to_f4(*(const uint2*)(q + (size_t)u * FDIM + lane * 4)));
    }
    return acc;
}

// mean agg: self fp32 (t0 path exact), neighbors fp16
__global__ void k_agg_mean128(const float* __restrict__ tself,
                              const __half* __restrict__ qnbr,
                              const float* __restrict__ b, int n) {
    int v = (blockIdx.x * blockDim.x + threadIdx.x) >> 5;
    int lane = threadIdx.x & 31;
    if (v >= n) return;
    int dt;
    float4 acc = gather_sum(qnbr, v, lane, dt);
    float inv = 1.0f / fmaxf((float)dt, 1.0f);
    float4 sf = *(const float4*)(tself + (size_t)v * FDIM + lane * 4);
    float4 bb = *(const float4*)(b + lane * 4);
    float4 o;
    o.x = fmaxf(sf.x + acc.x * inv + bb.x, 0.f);
    o.y = fmaxf(sf.y + acc.y * inv + bb.y, 0.f);
    o.z = fmaxf(sf.z + acc.z * inv + bb.z, 0.f);
    o.w = fmaxf(sf.w + acc.w * inv + bb.w, 0.f);
    store_split4((size_t)v * FDIM + lane * 4, o);
}

// gcn agg: self AND neighbors from fp16 mirror (self weight ~1/17, negligible)
__global__ void k_agg_gcn128(const __half* __restrict__ q,
                             const float* __restrict__ b, int n) {
    int v = (blockIdx.x * blockDim.x + threadIdx.x) >> 5;
    int lane = threadIdx.x & 31;
    if (v >= n) return;
    int dt;
    float4 acc = gather_sum(q, v, lane, dt);
    float4 sf = h4_to_f4(*(const uint2*)(q + (size_t)v * FDIM + lane * 4));
    acc4(acc, sf);
    float inv = 1.0f / ((float)dt + 1.0f);
    float4 bb = *(const float4*)(b + lane * 4);
    float4 o;
    o.x = fmaxf(acc.x * inv + bb.x, 0.f);
    o.y = fmaxf(acc.y * inv + bb.y, 0.f);
    o.z = fmaxf(acc.z * inv + bb.z, 0.f);
    o.w = fmaxf(acc.w * inv + bb.w, 0.f);
    store_split4((size_t)v * FDIM + lane * 4, o);
}

// layer3 (fp32): t is [n,64] = self|neigh
__global__ void k_agg_mean32(const float* __restrict__ t,
                             const float* __restrict__ b,
                             float* __restrict__ out, int n) {
    int v = (blockIdx.x * blockDim.x + threadIdx.x) >> 5;
    int lane = threadIdx.x & 31;
    if (v >= n) return;
    int dt = g_cnt[v];
    int L = dt < CAP ? dt : CAP;
    const int* cp = g_col + v * CAP;
    float acc = 0.f;
    int j = 0;
    for (; j + 4 <= L; j += 4) {
        int4 u = *(const int4*)(cp + j);
        float a0 = t[(size_t)u.x * 64 + 32 + lane];
        float a1 = t[(size_t)u.y * 64 + 32 + lane];
        float a2 = t[(size_t)u.z * 64 + 32 + lane];
        float a3 = t[(size_t)u.w * 64 + 32 + lane];
        acc += a0 + a1 + a2 + a3;
    }
    for (; j < L; j++) acc += t[(size_t)cp[j] * 64 + 32 + lane];
    float inv = 1.0f / fmaxf((float)dt, 1.0f);
    out[(size_t)v * OUTF + lane] = t[(size_t)v * 64 + lane] + acc * inv + b[lane];
}

// ---------------------------------------------------------------------------
extern "C" void kernel_launch(void* const* d_in, const int* in_sizes, int n_in,
                              void* d_out, int out_size) {
    const float* x       = (const float*)d_in[0];
    const void*  src     = d_in[1];
    const void*  dst     = d_in[2];
    const float* Wself0  = (const float*)d_in[3];
    const float* Wneigh0 = (const float*)d_in[4];
    const float* b0      = (const float*)d_in[5];
    const float* Wneigh1 = (const float*)d_in[6];
    const float* b1      = (const float*)d_in[7];
    const float* Wneigh2 = (const float*)d_in[8];
    const float* b2      = (const float*)d_in[9];
    const float* Wself3  = (const float*)d_in[10];
    const float* Wneigh3 = (const float*)d_in[11];
    const float* b3      = (const float*)d_in[12];
    float* out = (float*)d_out;

    int n = in_sizes[0] / FDIM;
    int e = in_sizes[1];

    bf16 *ah, *al, *wh, *wl;
    float *t0;
    __half *q;
    int* is64p;
    cudaGetSymbolAddress((void**)&ah, g_ah);
    cudaGetSymbolAddress((void**)&al, g_al);
    cudaGetSymbolAddress((void**)&wh, g_wh);
    cudaGetSymbolAddress((void**)&wl, g_wl);
    cudaGetSymbolAddress((void**)&t0, g_t0);
    cudaGetSymbolAddress((void**)&q,  g_q);
    cudaGetSymbolAddress((void**)&is64p, g_is64);

    static cudaStream_t s1 = nullptr, s2 = nullptr;
    static cudaEvent_t eFork = nullptr, eCSR = nullptr, eW = nullptr,
                       eN = nullptr, eG1 = nullptr;
    if (!s1) {
        cudaStreamCreateWithFlags(&s1, cudaStreamNonBlocking);
        cudaStreamCreateWithFlags(&s2, cudaStreamNonBlocking);
        cudaEventCreateWithFlags(&eFork, cudaEventDisableTiming);
        cudaEventCreateWithFlags(&eCSR,  cudaEventDisableTiming);
        cudaEventCreateWithFlags(&eW,    cudaEventDisableTiming);
        cudaEventCreateWithFlags(&eN,    cudaEventDisableTiming);
        cudaEventCreateWithFlags(&eG1,   cudaEventDisableTiming);
    }

    int aggBlocks = (n + 7) / 8;
    int gemmBlocks = (n + 127) / 128;

    // fork
    cudaMemsetAsync(is64p, 1, 4);               // nonzero => int64 until refuted
    cudaEventRecord(eFork, 0);

    // s1: CSR build
    cudaStreamWaitEvent(s1, eFork, 0);
    k_zero_detect<<<1024, 256, 0, s1>>>((const int*)dst, n, e);
    k_scatter<<<1024, 256, 0, s1>>>(src, dst, e);
    cudaEventRecord(eCSR, s1);

    // s2: weight split
    cudaStreamWaitEvent(s2, eFork, 0);
    k_wsplit<<<(73728 + 255) / 256, 256, 0, s2>>>(Wself0, Wneigh0, Wneigh1,
                                                  Wneigh2, Wself3, Wneigh3);
    cudaEventRecord(eW, s2);

    // s0: norm
    k_norm<<<aggBlocks, 256>>>(x, n);
    cudaEventRecord(eN, 0);

    // s0: L0 self GEMM -> t0 (fp32)
    cudaStreamWaitEvent(0, eW, 0);
    k_gemm_bf<128, false><<<gemmBlocks, 256>>>(ah, al, wh, wl, t0, q, n);

    // s2: L0 neigh GEMM -> q (fp16 only), parallel with self GEMM
    cudaStreamWaitEvent(s2, eN, 0);
    k_gemm_bf<128, true><<<gemmBlocks, 256, 0, s2>>>(ah, al, wh + 16384,
                                                     wl + 16384, t0, q, n);
    cudaEventRecord(eG1, s2);

    // s0: join, then serial tail
    cudaStreamWaitEvent(0, eCSR, 0);
    cudaStreamWaitEvent(0, eG1, 0);
    k_agg_mean128<<<aggBlocks, 256>>>(t0, q, b0, n);

    k_gemm_bf<128, true><<<gemmBlocks, 256>>>(ah, al, wh + 32768, wl + 32768,
                                              t0, q, n);
    k_agg_gcn128<<<aggBlocks, 256>>>(q, b1, n);

    k_gemm_bf<128, true><<<gemmBlocks, 256>>>(ah, al, wh + 49152, wl + 49152,
                                              t0, q, n);
    k_agg_gcn128<<<aggBlocks, 256>>>(q, b2, n);

    // L3 GEMM (M=64, fp32) -> t0 [n,64], then final agg
    k_gemm_bf<64, false><<<gemmBlocks, 256>>>(ah, al, wh + 65536, wl + 65536,
                                              t0, q, n);
    k_agg_mean32<<<aggBlocks, 256>>>(t0, b3, out, n);
}

// round 11
// speedup vs baseline: 1.3188x; 1.1381x over previous
#include <cuda_runtime.h>
#include <cuda_fp16.h>
#include <cstdint>

// GraphSAGE: N=50000, E=800000, 128 -> 128 -> 128 -> 32
// ALL-FP16 activation pipeline:
//  - Activations stored ONLY as fp16 (ping-pong qA/qB); aggs/norm write fp16.
//  - GEMM: mma.sync m16n8k16 fp16, A fp16 (exact), W 2-term fp16 split
//    (wh + wl, ~22-bit weights) -> 2 MMAs per tile instead of 3.
//  - Mean-agg self term fp32 (t0); layer 3 fully fp32.
//  - Bucket CSR (96 slots) + fork-join streams (CSR/wsplit off critical path).

#define NN 50000
#define FDIM 128
#define OUTF 32
#define CAP 96

__device__ __half g_wh[73728];
__device__ __half g_wl[73728];
__device__ float  g_t0[NN * FDIM];
__device__ __half g_qa[NN * FDIM];
__device__ __half g_qb[NN * FDIM];
__device__ int    g_cnt[NN];
__device__ int    g_col[NN * CAP];
__device__ int    g_is64;

// ---------------------------------------------------------------------------
__device__ __forceinline__ void split_fp16(float v, __half& hi, __half& lo) {
    hi = __float2half_rn(v);
    lo = __float2half_rn(v - __half2float(hi));
}

__device__ __forceinline__ void store_h4(__half* q, size_t off, float4 o) {
    *(__half2*)(q + off)     = __float22half2_rn(make_float2(o.x, o.y));
    *(__half2*)(q + off + 2) = __float22half2_rn(make_float2(o.z, o.w));
}

__device__ __forceinline__ void cpa16(uint32_t dst, const void* src, int szz) {
    asm volatile("cp.async.ca.shared.global [%0], [%1], 16, %2;"
                 :: "r"(dst), "l"(src), "r"(szz));
}
#define CP_COMMIT asm volatile("cp.async.commit_group;" ::: "memory")
#define CP_WAIT1  asm volatile("cp.async.wait_group 1;" ::: "memory")
#define CP_WAIT0  asm volatile("cp.async.wait_group 0;" ::: "memory")

__device__ __forceinline__ void ldsm4(uint32_t r[4], uint32_t addr) {
    asm volatile("ldmatrix.sync.aligned.m8n8.x4.shared.b16 {%0,%1,%2,%3}, [%4];"
                 : "=r"(r[0]), "=r"(r[1]), "=r"(r[2]), "=r"(r[3]) : "r"(addr));
}
__device__ __forceinline__ void ldsm4t(uint32_t r[4], uint32_t addr) {
    asm volatile("ldmatrix.sync.aligned.m8n8.x4.trans.shared.b16 {%0,%1,%2,%3}, [%4];"
                 : "=r"(r[0]), "=r"(r[1]), "=r"(r[2]), "=r"(r[3]) : "r"(addr));
}
__device__ __forceinline__ void mma16816(float d[4], const uint32_t a[4],
                                         const uint32_t* b) {
    asm volatile(
        "mma.sync.aligned.m16n8k16.row.col.f32.f16.f16.f32 "
        "{%0,%1,%2,%3}, {%4,%5,%6,%7}, {%8,%9}, {%0,%1,%2,%3};"
        : "+f"(d[0]), "+f"(d[1]), "+f"(d[2]), "+f"(d[3])
        : "r"(a[0]), "r"(a[1]), "r"(a[2]), "r"(a[3]), "r"(b[0]), "r"(b[1]));
}

// ---------------------------------------------------------------------------
__device__ __forceinline__ int eidx(const void* p, int i, int is64) {
    return is64 ? (int)((const long long*)p)[i] : ((const int*)p)[i];
}

__global__ void k_zero_detect(const int* w, int n, int e) {
    for (int i = blockIdx.x * blockDim.x + threadIdx.x; i < e;
         i += gridDim.x * blockDim.x) {
        if (i < n) g_cnt[i] = 0;
        if ((i & 1) && w[i] != 0) g_is64 = 0;
    }
}

__global__ void k_scatter(const void* src, const void* dst, int e) {
    int is64 = g_is64;
    for (int i = blockIdx.x * blockDim.x + threadIdx.x; i < e;
         i += gridDim.x * blockDim.x) {
        int d = eidx(dst, i, is64);
        int p = atomicAdd(&g_cnt[d], 1);
        if (p < CAP) g_col[d * CAP + p] = eidx(src, i, is64);
    }
}

// ---------------------------------------------------------------------------
// Weight pre-split (fp16 hi/lo):
// [0)=Wself0 [16384)=Wneigh0 [32768)=Wneigh1 [49152)=Wneigh2
// [65536, 73728) = concat(Wself3 | Wneigh3) as [128 x 64]
// ---------------------------------------------------------------------------
__global__ void k_wsplit(const float* __restrict__ ws0, const float* __restrict__ wn0,
                         const float* __restrict__ wn1, const float* __restrict__ wn2,
                         const float* __restrict__ ws3, const float* __restrict__ wn3) {
    int i = blockIdx.x * blockDim.x + threadIdx.x;
    if (i >= 73728) return;
    float v;
    if (i < 16384) v = ws0[i];
    else if (i < 32768) v = wn0[i - 16384];
    else if (i < 49152) v = wn1[i - 32768];
    else if (i < 65536) v = wn2[i - 49152];
    else {
        int j = i - 65536, r = j >> 6, c = j & 63;
        v = (c < 32) ? ws3[r * 32 + c] : wn3[r * 32 + c - 32];
    }
    __half hi, lo;
    split_fp16(v, hi, lo);
    g_wh[i] = hi;
    g_wl[i] = lo;
}

// ---------------------------------------------------------------------------
// L2 normalize -> fp16
// ---------------------------------------------------------------------------
__global__ void k_norm(const float* __restrict__ x, __half* __restrict__ q, int n) {
    int v = (blockIdx.x * blockDim.x + threadIdx.x) >> 5;
    int lane = threadIdx.x & 31;
    if (v >= n) return;
    float4 a = *(const float4*)(x + (size_t)v * FDIM + lane * 4);
    float ss = a.x * a.x + a.y * a.y + a.z * a.z + a.w * a.w;
    #pragma unroll
    for (int o = 16; o; o >>= 1) ss += __shfl_xor_sync(0xFFFFFFFFu, ss, o);
    float s = 1.0f / fmaxf(sqrtf(ss), 1e-12f);
    a.x *= s; a.y *= s; a.z *= s; a.w *= s;
    store_h4(q, (size_t)v * FDIM + lane * 4, a);
}

// ---------------------------------------------------------------------------
// fp16 tensor GEMM: A[n,128] fp16 @ (Wh+Wl)[128,M] fp16 -> fp32 acc.
// QONLY=false: fp32 C out; QONLY=true: fp16 Q out.
// ---------------------------------------------------------------------------
template <int M>
__device__ __forceinline__ void stage_chunk(
    uint32_t dA, uint32_t dWh, uint32_t dWl,
    const __half* __restrict__ Ag,
    const __half* __restrict__ Wgh, const __half* __restrict__ Wgl,
    int row0, int k0, int n, int tid) {
    // A: 128 rows x 16 k fp16 (32B = 2 x 16B)
    #pragma unroll
    for (int i = tid; i < 256; i += 256) {
        int r = i >> 1, seg = i & 1;
        int row = row0 + r;
        int ok = (row < n) ? 16 : 0;
        size_t so = (size_t)(ok ? row : 0) * 128 + k0 + seg * 8;
        uint32_t dof = (uint32_t)(r * 24 + seg * 8) * 2;
        cpa16(dA + dof, Ag + so, ok);
    }
    constexpr int CW = M / 8;
    #pragma unroll
    for (int i = tid; i < 2 * 16 * CW; i += 256) {
        int half_ = i / (16 * CW), rem = i % (16 * CW);
        int r = rem / CW, seg = rem % CW;
        size_t so = (size_t)(k0 + r) * M + seg * 8;
        uint32_t dof = (uint32_t)(r * (M + 8) + seg * 8) * 2;
        if (half_ == 0) cpa16(dWh + dof, Wgh + so, 16);
        else            cpa16(dWl + dof, Wgl + so, 16);
    }
}

template <int M, bool QONLY>
__global__ void __launch_bounds__(256) k_gemm_h(
    const __half* __restrict__ Ag,
    const __half* __restrict__ Wgh, const __half* __restrict__ Wgl,
    float* __restrict__ C, __half* __restrict__ Q, int n) {
    constexpr int LDA = 24;
    constexpr int LDB = M + 8;
    constexpr int NT  = M / 16;
    __shared__ __half A[2][128 * LDA];
    __shared__ __half Wh[2][16 * LDB], Wl[2][16 * LDB];

    int tid = threadIdx.x;
    int lane = tid & 31, wid = tid >> 5;
    int row0 = blockIdx.x * 128;

    float acc[NT][2][4];
    #pragma unroll
    for (int t = 0; t < NT; t++)
        #pragma unroll
        for (int s = 0; s < 2; s++)
            #pragma unroll
            for (int c = 0; c < 4; c++) acc[t][s][c] = 0.f;

    uint32_t sA[2]  = {(uint32_t)__cvta_generic_to_shared(A[0]),
                       (uint32_t)__cvta_generic_to_shared(A[1])};
    uint32_t sWh[2] = {(uint32_t)__cvta_generic_to_shared(Wh[0]),
                       (uint32_t)__cvta_generic_to_shared(Wh[1])};
    uint32_t sWl[2] = {(uint32_t)__cvta_generic_to_shared(Wl[0]),
                       (uint32_t)__cvta_generic_to_shared(Wl[1])};

    stage_chunk<M>(sA[0], sWh[0], sWl[0], Ag, Wgh, Wgl, row0, 0, n, tid);
    CP_COMMIT;

    #pragma unroll
    for (int c = 0; c < 8; c++) {
        int b = c & 1;
        if (c < 7) {
            int nb = (c + 1) & 1;
            stage_chunk<M>(sA[nb], sWh[nb], sWl[nb], Ag, Wgh, Wgl,
                           row0, (c + 1) * 16, n, tid);
            CP_COMMIT;
            CP_WAIT1;
        } else {
            CP_WAIT0;
        }
        __syncthreads();

        uint32_t aoff = ((wid * 16 + (lane & 15)) * LDA + (lane >> 4) * 8) * 2;
        uint32_t a[4];
        ldsm4(a, sA[b] + aoff);
        #pragma unroll
        for (int nt = 0; nt < NT; nt++) {
            uint32_t boff = ((lane & 15) * LDB + nt * 16 + (lane >> 4) * 8) * 2;
            uint32_t bh[4], bl[4];
            ldsm4t(bh, sWh[b] + boff);
            ldsm4t(bl, sWl[b] + boff);
            mma16816(acc[nt][0], a, bh + 0);
            mma16816(acc[nt][1], a, bh + 2);
            mma16816(acc[nt][0], a, bl + 0);
            mma16816(acc[nt][1], a, bl + 2);
        }
        __syncthreads();
    }

    int g = lane >> 2, tg = lane & 3;
    int r0 = row0 + wid * 16 + g;
    #pragma unroll
    for (int nt = 0; nt < NT; nt++) {
        #pragma unroll
        for (int s = 0; s < 2; s++) {
            int col = nt * 16 + s * 8 + tg * 2;
            float2 v01 = make_float2(acc[nt][s][0], acc[nt][s][1]);
            float2 v23 = make_float2(acc[nt][s][2], acc[nt][s][3]);
            if (QONLY) {
                if (r0 < n)
                    *(__half2*)(Q + (size_t)r0 * M + col) = __float22half2_rn(v01);
                if (r0 + 8 < n)
                    *(__half2*)(Q + (size_t)(r0 + 8) * M + col) =
                        __float22half2_rn(v23);
            } else {
                if (r0 < n)
                    *(float2*)(C + (size_t)r0 * M + col) = v01;
                if (r0 + 8 < n)
                    *(float2*)(C + (size_t)(r0 + 8) * M + col) = v23;
            }
        }
    }
}

// ---------------------------------------------------------------------------
// Aggregations: warp per node, bucket CSR, unroll-4 fp16 gathers, fp16 out.
// ---------------------------------------------------------------------------
__device__ __forceinline__ float4 h4_to_f4(uint2 raw) {
    __half2 p0 = *(__half2*)&raw.x;
    __half2 p1 = *(__half2*)&raw.y;
    float2 f0 = __half22float2(p0), f1 = __half22float2(p1);
    return make_float4(f0.x, f0.y, f1.x, f1.y);
}
__device__ __forceinline__ void acc4(float4& a, float4 t) {
    a.x += t.x; a.y += t.y; a.z += t.z; a.w += t.w;
}

__device__ __forceinline__ float4 gather_sum(const __half* __restrict__ q,
                                             int v, int lane, int& dt) {
    dt = g_cnt[v];
    int L = dt < CAP ? dt : CAP;
    const int* cp = g_col + v * CAP;
    float4 acc = make_float4(0.f, 0.f, 0.f, 0.f);
    int j = 0;
    for (; j + 4 <= L; j += 4) {
        int4 u = *(const int4*)(cp + j);
        uint2 a0 = *(const uint2*)(q + (size_t)u.x * FDIM + lane * 4);
        uint2 a1 = *(const uint2*)(q + (size_t)u.y * FDIM + lane * 4);
        uint2 a2 = *(const uint2*)(q + (size_t)u.z * FDIM + lane * 4);
        uint2 a3 = *(const uint2*)(q + (size_t)u.w * FDIM + lane * 4);
        acc4(acc, h4_to_f4(a0)); acc4(acc, h4_to_f4(a1));
        acc4(acc, h4_to_f4(a2)); acc4(acc, h4_to_f4(a3));
    }
    for (; j < L; j++) {
        int u = cp[j];
        acc4(acc, h4_to_f4(*(const uint2*)(q + (size_t)u * FDIM + lane * 4)));
    }
    return acc;
}

// mean agg: self fp32 (exact), neighbors fp16; fp16 out
__global__ void k_agg_mean128(const float* __restrict__ tself,
                              const __half* __restrict__ qnbr,
                              const float* __restrict__ b,
                              __half* __restrict__ qout, int n) {
    int v = (blockIdx.x * blockDim.x + threadIdx.x) >> 5;
    int lane = threadIdx.x & 31;
    if (v >= n) return;
    int dt;
    float4 acc = gather_sum(qnbr, v, lane, dt);
    float inv = 1.0f / fmaxf((float)dt, 1.0f);
    float4 sf = *(const float4*)(tself + (size_t)v * FDIM + lane * 4);
    float4 bb = *(const float4*)(b + lane * 4);
    float4 o;
    o.x = fmaxf(sf.x + acc.x * inv + bb.x, 0.f);
    o.y = fmaxf(sf.y + acc.y * inv + bb.y, 0.f);
    o.z = fmaxf(sf.z + acc.z * inv + bb.z, 0.f);
    o.w = fmaxf(sf.w + acc.w * inv + bb.w, 0.f);
    store_h4(qout, (size_t)v * FDIM + lane * 4, o);
}

// gcn agg: self + neighbors from fp16; fp16 out
__global__ void k_agg_gcn128(const __half* __restrict__ qin,
                             const float* __restrict__ b,
                             __half* __restrict__ qout, int n) {
    int v = (blockIdx.x * blockDim.x + threadIdx.x) >> 5;
    int lane = threadIdx.x & 31;
    if (v >= n) return;
    int dt;
    float4 acc = gather_sum(qin, v, lane, dt);
    float4 sf = h4_to_f4(*(const uint2*)(qin + (size_t)v * FDIM + lane * 4));
    acc4(acc, sf);
    float inv = 1.0f / ((float)dt + 1.0f);
    float4 bb = *(const float4*)(b + lane * 4);
    float4 o;
    o.x = fmaxf(acc.x * inv + bb.x, 0.f);
    o.y = fmaxf(acc.y * inv + bb.y, 0.f);
    o.z = fmaxf(acc.z * inv + bb.z, 0.f);
    o.w = fmaxf(acc.w * inv + bb.w, 0.f);
    store_h4(qout, (size_t)v * FDIM + lane * 4, o);
}

// layer3 (fp32): t is [n,64] = self|neigh
__global__ void k_agg_mean32(const float* __restrict__ t,
                             const float* __restrict__ b,
                             float* __restrict__ out, int n) {
    int v = (blockIdx.x * blockDim.x + threadIdx.x) >> 5;
    int lane = threadIdx.x & 31;
    if (v >= n) return;
    int dt = g_cnt[v];
    int L = dt < CAP ? dt : CAP;
    const int* cp = g_col + v * CAP;
    float acc = 0.f;
    int j = 0;
    for (; j + 4 <= L; j += 4) {
        int4 u = *(const int4*)(cp + j);
        float a0 = t[(size_t)u.x * 64 + 32 + lane];
        float a1 = t[(size_t)u.y * 64 + 32 + lane];
        float a2 = t[(size_t)u.z * 64 + 32 + lane];
        float a3 = t[(size_t)u.w * 64 + 32 + lane];
        acc += a0 + a1 + a2 + a3;
    }
    for (; j < L; j++) acc += t[(size_t)cp[j] * 64 + 32 + lane];
    float inv = 1.0f / fmaxf((float)dt, 1.0f);
    out[(size_t)v * OUTF + lane] = t[(size_t)v * 64 + lane] + acc * inv + b[lane];
}

// ---------------------------------------------------------------------------
extern "C" void kernel_launch(void* const* d_in, const int* in_sizes, int n_in,
                              void* d_out, int out_size) {
    const float* x       = (const float*)d_in[0];
    const void*  src     = d_in[1];
    const void*  dst     = d_in[2];
    const float* Wself0  = (const float*)d_in[3];
    const float* Wneigh0 = (const float*)d_in[4];
    const float* b0      = (const float*)d_in[5];
    const float* Wneigh1 = (const float*)d_in[6];
    const float* b1      = (const float*)d_in[7];
    const float* Wneigh2 = (const float*)d_in[8];
    const float* b2      = (const float*)d_in[9];
    const float* Wself3  = (const float*)d_in[10];
    const float* Wneigh3 = (const float*)d_in[11];
    const float* b3      = (const float*)d_in[12];
    float* out = (float*)d_out;

    int n = in_sizes[0] / FDIM;
    int e = in_sizes[1];

    __half *wh, *wl, *qa, *qb;
    float* t0;
    int* is64p;
    cudaGetSymbolAddress((void**)&wh, g_wh);
    cudaGetSymbolAddress((void**)&wl, g_wl);
    cudaGetSymbolAddress((void**)&qa, g_qa);
    cudaGetSymbolAddress((void**)&qb, g_qb);
    cudaGetSymbolAddress((void**)&t0, g_t0);
    cudaGetSymbolAddress((void**)&is64p, g_is64);

    static cudaStream_t s1 = nullptr, s2 = nullptr;
    static cudaEvent_t eFork = nullptr, eCSR = nullptr, eW = nullptr,
                       eN = nullptr, eG1 = nullptr;
    if (!s1) {
        cudaStreamCreateWithFlags(&s1, cudaStreamNonBlocking);
        cudaStreamCreateWithFlags(&s2, cudaStreamNonBlocking);
        cudaEventCreateWithFlags(&eFork, cudaEventDisableTiming);
        cudaEventCreateWithFlags(&eCSR,  cudaEventDisableTiming);
        cudaEventCreateWithFlags(&eW,    cudaEventDisableTiming);
        cudaEventCreateWithFlags(&eN,    cudaEventDisableTiming);
        cudaEventCreateWithFlags(&eG1,   cudaEventDisableTiming);
    }

    int aggBlocks = (n + 7) / 8;
    int gemmBlocks = (n + 127) / 128;

    // fork
    cudaMemsetAsync(is64p, 1, 4);               // nonzero => int64 until refuted
    cudaEventRecord(eFork, 0);

    // s1: CSR build
    cudaStreamWaitEvent(s1, eFork, 0);
    k_zero_detect<<<1024, 256, 0, s1>>>((const int*)dst, n, e);
    k_scatter<<<1024, 256, 0, s1>>>(src, dst, e);
    cudaEventRecord(eCSR, s1);

    // s2: weight split
    cudaStreamWaitEvent(s2, eFork, 0);
    k_wsplit<<<(73728 + 255) / 256, 256, 0, s2>>>(Wself0, Wneigh0, Wneigh1,
                                                  Wneigh2, Wself3, Wneigh3);
    cudaEventRecord(eW, s2);

    // s0: norm -> qa (fp16)
    k_norm<<<aggBlocks, 256>>>(x, qa, n);
    cudaEventRecord(eN, 0);

    // s0: L0 self GEMM qa -> t0 (fp32)
    cudaStreamWaitEvent(0, eW, 0);
    k_gemm_h<128, false><<<gemmBlocks, 256>>>(qa, wh, wl, t0, qb, n);

    // s2: L0 neigh GEMM qa -> qb (fp16), parallel
    cudaStreamWaitEvent(s2, eN, 0);
    k_gemm_h<128, true><<<gemmBlocks, 256, 0, s2>>>(qa, wh + 16384, wl + 16384,
                                                    t0, qb, n);
    cudaEventRecord(eG1, s2);

    // s0: join, serial tail (ping-pong qa/qb)
    cudaStreamWaitEvent(0, eCSR, 0);
    cudaStreamWaitEvent(0, eG1, 0);
    k_agg_mean128<<<aggBlocks, 256>>>(t0, qb, b0, qa, n);

    k_gemm_h<128, true><<<gemmBlocks, 256>>>(qa, wh + 32768, wl + 32768,
                                             t0, qb, n);
    k_agg_gcn128<<<aggBlocks, 256>>>(qb, b1, qa, n);

    k_gemm_h<128, true><<<gemmBlocks, 256>>>(qa, wh + 49152, wl + 49152,
                                             t0, qb, n);
    k_agg_gcn128<<<aggBlocks, 256>>>(qb, b2, qa, n);

    // L3 GEMM (M=64, fp32 out) -> t0 [n,64], then final agg
    k_gemm_h<64, false><<<gemmBlocks, 256>>>(qa, wh + 65536, wl + 65536,
                                             t0, qb, n);
    k_agg_mean32<<<aggBlocks, 256>>>(t0, b3, out, n);
}

// round 12
// speedup vs baseline: 1.3623x; 1.0330x over previous
#include <cuda_runtime.h>
#include <cuda_fp16.h>
#include <cstdint>

// GraphSAGE: N=50000, E=800000, 128 -> 128 -> 128 -> 32
// ALL-FP16 activation pipeline + PDL (programmatic dependent launch):
//  - Serial-tail kernels launch with ProgrammaticStreamSerialization; each
//    does independent prologue work (W staging / CSR index reads) before
//    cudaGridDependencySynchronize(), hiding launch latency + pred drain.
//  - GEMM: mma.sync m16n8k16 fp16, A fp16 exact, W 2-term fp16 split.
//  - Mean-agg self term fp32 (t0); layer 3 fully fp32.
//  - Bucket CSR (96 slots) + fork-join streams.

#define NN 50000
#define FDIM 128
#define OUTF 32
#define CAP 96

__device__ __half g_wh[73728];
__device__ __half g_wl[73728];
__device__ float  g_t0[NN * FDIM];
__device__ __half g_qa[NN * FDIM];
__device__ __half g_qb[NN * FDIM];
__device__ int    g_cnt[NN];
__device__ int    g_col[NN * CAP];
__device__ int    g_is64;

// ---------------------------------------------------------------------------
__device__ __forceinline__ void split_fp16(float v, __half& hi, __half& lo) {
    hi = __float2half_rn(v);
    lo = __float2half_rn(v - __half2float(hi));
}

__device__ __forceinline__ void store_h4(__half* q, size_t off, float4 o) {
    *(__half2*)(q + off)     = __float22half2_rn(make_float2(o.x, o.y));
    *(__half2*)(q + off + 2) = __float22half2_rn(make_float2(o.z, o.w));
}

__device__ __forceinline__ void cpa16(uint32_t dst, const void* src, int szz) {
    asm volatile("cp.async.ca.shared.global [%0], [%1], 16, %2;"
                 :: "r"(dst), "l"(src), "r"(szz));
}
#define CP_COMMIT asm volatile("cp.async.commit_group;" ::: "memory")
#define CP_WAIT1  asm volatile("cp.async.wait_group 1;" ::: "memory")
#define CP_WAIT0  asm volatile("cp.async.wait_group 0;" ::: "memory")

__device__ __forceinline__ void ldsm4(uint32_t r[4], uint32_t addr) {
    asm volatile("ldmatrix.sync.aligned.m8n8.x4.shared.b16 {%0,%1,%2,%3}, [%4];"
                 : "=r"(r[0]), "=r"(r[1]), "=r"(r[2]), "=r"(r[3]) : "r"(addr));
}
__device__ __forceinline__ void ldsm4t(uint32_t r[4], uint32_t addr) {
    asm volatile("ldmatrix.sync.aligned.m8n8.x4.trans.shared.b16 {%0,%1,%2,%3}, [%4];"
                 : "=r"(r[0]), "=r"(r[1]), "=r"(r[2]), "=r"(r[3]) : "r"(addr));
}
__device__ __forceinline__ void mma16816(float d[4], const uint32_t a[4],
                                         const uint32_t* b) {
    asm volatile(
        "mma.sync.aligned.m16n8k16.row.col.f32.f16.f16.f32 "
        "{%0,%1,%2,%3}, {%4,%5,%6,%7}, {%8,%9}, {%0,%1,%2,%3};"
        : "+f"(d[0]), "+f"(d[1]), "+f"(d[2]), "+f"(d[3])
        : "r"(a[0]), "r"(a[1]), "r"(a[2]), "r"(a[3]), "r"(b[0]), "r"(b[1]));
}

// ---------------------------------------------------------------------------
__device__ __forceinline__ int eidx(const void* p, int i, int is64) {
    return is64 ? (int)((const long long*)p)[i] : ((const int*)p)[i];
}

__global__ void k_zero_detect(const int* w, int n, int e) {
    for (int i = blockIdx.x * blockDim.x + threadIdx.x; i < e;
         i += gridDim.x * blockDim.x) {
        if (i < n) g_cnt[i] = 0;
        if ((i & 1) && w[i] != 0) g_is64 = 0;
    }
}

__global__ void k_scatter(const void* src, const void* dst, int e) {
    int is64 = g_is64;
    for (int i = blockIdx.x * blockDim.x + threadIdx.x; i < e;
         i += gridDim.x * blockDim.x) {
        int d = eidx(dst, i, is64);
        int p = atomicAdd(&g_cnt[d], 1);
        if (p < CAP) g_col[d * CAP + p] = eidx(src, i, is64);
    }
}

// ---------------------------------------------------------------------------
// Weight pre-split (fp16 hi/lo):
// [0)=Wself0 [16384)=Wneigh0 [32768)=Wneigh1 [49152)=Wneigh2
// [65536, 73728) = concat(Wself3 | Wneigh3) as [128 x 64]
// ---------------------------------------------------------------------------
__global__ void k_wsplit(const float* __restrict__ ws0, const float* __restrict__ wn0,
                         const float* __restrict__ wn1, const float* __restrict__ wn2,
                         const float* __restrict__ ws3, const float* __restrict__ wn3) {
    int i = blockIdx.x * blockDim.x + threadIdx.x;
    if (i >= 73728) return;
    float v;
    if (i < 16384) v = ws0[i];
    else if (i < 32768) v = wn0[i - 16384];
    else if (i < 49152) v = wn1[i - 32768];
    else if (i < 65536) v = wn2[i - 49152];
    else {
        int j = i - 65536, r = j >> 6, c = j & 63;
        v = (c < 32) ? ws3[r * 32 + c] : wn3[r * 32 + c - 32];
    }
    __half hi, lo;
    split_fp16(v, hi, lo);
    g_wh[i] = hi;
    g_wl[i] = lo;
}

// ---------------------------------------------------------------------------
__global__ void k_norm(const float* __restrict__ x, __half* __restrict__ q, int n) {
    int v = (blockIdx.x * blockDim.x + threadIdx.x) >> 5;
    int lane = threadIdx.x & 31;
    if (v >= n) return;
    float4 a = *(const float4*)(x + (size_t)v * FDIM + lane * 4);
    float ss = a.x * a.x + a.y * a.y + a.z * a.z + a.w * a.w;
    #pragma unroll
    for (int o = 16; o; o >>= 1) ss += __shfl_xor_sync(0xFFFFFFFFu, ss, o);
    float s = 1.0f / fmaxf(sqrtf(ss), 1e-12f);
    a.x *= s; a.y *= s; a.z *= s; a.w *= s;
    store_h4(q, (size_t)v * FDIM + lane * 4, a);
}

// ---------------------------------------------------------------------------
// fp16 tensor GEMM with PDL: W chunk staged BEFORE grid-dependency sync
// (weights are ready), A staged after (depends on predecessor kernel).
// ---------------------------------------------------------------------------
template <int M>
__device__ __forceinline__ void stage_w(uint32_t dWh, uint32_t dWl,
                                        const __half* __restrict__ Wgh,
                                        const __half* __restrict__ Wgl,
                                        int k0, int tid) {
    constexpr int CW = M / 8;
    #pragma unroll
    for (int i = tid; i < 2 * 16 * CW; i += 256) {
        int half_ = i / (16 * CW), rem = i % (16 * CW);
        int r = rem / CW, seg = rem % CW;
        size_t so = (size_t)(k0 + r) * M + seg * 8;
        uint32_t dof = (uint32_t)(r * (M + 8) + seg * 8) * 2;
        if (half_ == 0) cpa16(dWh + dof, Wgh + so, 16);
        else            cpa16(dWl + dof, Wgl + so, 16);
    }
}

__device__ __forceinline__ void stage_a(uint32_t dA, const __half* __restrict__ Ag,
                                        int row0, int k0, int n, int tid) {
    // A chunk: 128 rows x 16 halves = 256 x 16B segments (1 per thread)
    int r = tid >> 1, seg = tid & 1;
    int row = row0 + r;
    int ok = (row < n) ? 16 : 0;
    size_t so = (size_t)(ok ? row : 0) * 128 + k0 + seg * 8;
    uint32_t dof = (uint32_t)(r * 24 + seg * 8) * 2;
    cpa16(dA + dof, Ag + so, ok);
}

template <int M, bool QONLY>
__global__ void __launch_bounds__(256) k_gemm_h(
    const __half* __restrict__ Ag,
    const __half* __restrict__ Wgh, const __half* __restrict__ Wgl,
    float* __restrict__ C, __half* __restrict__ Q, int n) {
    constexpr int LDA = 24;
    constexpr int LDB = M + 8;
    constexpr int NT  = M / 16;
    __shared__ __half A[2][128 * LDA];
    __shared__ __half Wh[2][16 * LDB], Wl[2][16 * LDB];

    int tid = threadIdx.x;
    int lane = tid & 31, wid = tid >> 5;
    int row0 = blockIdx.x * 128;

    float acc[NT][2][4];
    #pragma unroll
    for (int t = 0; t < NT; t++)
        #pragma unroll
        for (int s = 0; s < 2; s++)
            #pragma unroll
            for (int c = 0; c < 4; c++) acc[t][s][c] = 0.f;

    uint32_t sA[2]  = {(uint32_t)__cvta_generic_to_shared(A[0]),
                       (uint32_t)__cvta_generic_to_shared(A[1])};
    uint32_t sWh[2] = {(uint32_t)__cvta_generic_to_shared(Wh[0]),
                       (uint32_t)__cvta_generic_to_shared(Wh[1])};
    uint32_t sWl[2] = {(uint32_t)__cvta_generic_to_shared(Wl[0]),
                       (uint32_t)__cvta_generic_to_shared(Wl[1])};

    // prologue (independent of predecessor): W chunk 0
    stage_w<M>(sWh[0], sWl[0], Wgh, Wgl, 0, tid);
    CP_COMMIT;                         // group: W0

    cudaGridDependencySynchronize();   // wait for predecessor's A data

    stage_a(sA[0], Ag, row0, 0, n, tid);
    CP_COMMIT;                         // group: A0

    #pragma unroll
    for (int c = 0; c < 8; c++) {
        int b = c & 1;
        if (c < 7) {
            int nb = (c + 1) & 1;
            stage_w<M>(sWh[nb], sWl[nb], Wgh, Wgl, (c + 1) * 16, tid);
            stage_a(sA[nb], Ag, row0, (c + 1) * 16, n, tid);
            CP_COMMIT;
            CP_WAIT1;                  // chunks <= c resident
        } else {
            CP_WAIT0;
        }
        __syncthreads();

        uint32_t aoff = ((wid * 16 + (lane & 15)) * LDA + (lane >> 4) * 8) * 2;
        uint32_t a[4];
        ldsm4(a, sA[b] + aoff);
        #pragma unroll
        for (int nt = 0; nt < NT; nt++) {
            uint32_t boff = ((lane & 15) * LDB + nt * 16 + (lane >> 4) * 8) * 2;
            uint32_t bh[4], bl[4];
            ldsm4t(bh, sWh[b] + boff);
            ldsm4t(bl, sWl[b] + boff);
            mma16816(acc[nt][0], a, bh + 0);
            mma16816(acc[nt][1], a, bh + 2);
            mma16816(acc[nt][0], a, bl + 0);
            mma16816(acc[nt][1], a, bl + 2);
        }
        __syncthreads();
    }

    int g = lane >> 2, tg = lane & 3;
    int r0 = row0 + wid * 16 + g;
    #pragma unroll
    for (int nt = 0; nt < NT; nt++) {
        #pragma unroll
        for (int s = 0; s < 2; s++) {
            int col = nt * 16 + s * 8 + tg * 2;
            float2 v01 = make_float2(acc[nt][s][0], acc[nt][s][1]);
            float2 v23 = make_float2(acc[nt][s][2], acc[nt][s][3]);
            if (QONLY) {
                if (r0 < n)
                    *(__half2*)(Q + (size_t)r0 * M + col) = __float22half2_rn(v01);
                if (r0 + 8 < n)
                    *(__half2*)(Q + (size_t)(r0 + 8) * M + col) =
                        __float22half2_rn(v23);
            } else {
                if (r0 < n)
                    *(float2*)(C + (size_t)r0 * M + col) = v01;
                if (r0 + 8 < n)
                    *(float2*)(C + (size_t)(r0 + 8) * M + col) = v23;
            }
        }
    }
}

// ---------------------------------------------------------------------------
// Aggregations: warp per node, bucket CSR, unroll-4 fp16 gathers, fp16 out.
// PDL: CSR count read before grid-dependency sync; gathers/writes after.
// ---------------------------------------------------------------------------
__device__ __forceinline__ float4 h4_to_f4(uint2 raw) {
    __half2 p0 = *(__half2*)&raw.x;
    __half2 p1 = *(__half2*)&raw.y;
    float2 f0 = __half22float2(p0), f1 = __half22float2(p1);
    return make_float4(f0.x, f0.y, f1.x, f1.y);
}
__device__ __forceinline__ void acc4(float4& a, float4 t) {
    a.x += t.x; a.y += t.y; a.z += t.z; a.w += t.w;
}

__device__ __forceinline__ float4 gather_sum(const __half* __restrict__ q,
                                             int v, int lane, int dt) {
    int L = dt < CAP ? dt : CAP;
    const int* cp = g_col + v * CAP;
    float4 acc = make_float4(0.f, 0.f, 0.f, 0.f);
    int j = 0;
    for (; j + 4 <= L; j += 4) {
        int4 u = *(const int4*)(cp + j);
        uint2 a0 = *(const uint2*)(q + (size_t)u.x * FDIM + lane * 4);
        uint2 a1 = *(const uint2*)(q + (size_t)u.y * FDIM + lane * 4);
        uint2 a2 = *(const uint2*)(q + (size_t)u.z * FDIM + lane * 4);
        uint2 a3 = *(const uint2*)(q + (size_t)u.w * FDIM + lane * 4);
        acc4(acc, h4_to_f4(a0)); acc4(acc, h4_to_f4(a1));
        acc4(acc, h4_to_f4(a2)); acc4(acc, h4_to_f4(a3));
    }
    for (; j < L; j++) {
        int u = cp[j];
        acc4(acc, h4_to_f4(*(const uint2*)(q + (size_t)u * FDIM + lane * 4)));
    }
    return acc;
}

__global__ void k_agg_mean128(const float* __restrict__ tself,
                              const __half* __restrict__ qnbr,
                              const float* __restrict__ b,
                              __half* __restrict__ qout, int n) {
    int v = (blockIdx.x * blockDim.x + threadIdx.x) >> 5;
    int lane = threadIdx.x & 31;
    if (v >= n) { cudaGridDependencySynchronize(); return; }
    int dt = g_cnt[v];                 // CSR: ready (event-gated earlier)
    cudaGridDependencySynchronize();   // predecessor wrote tself/qnbr
    float4 acc = gather_sum(qnbr, v, lane, dt);
    float inv = 1.0f / fmaxf((float)dt, 1.0f);
    float4 sf = *(const float4*)(tself + (size_t)v * FDIM + lane * 4);
    float4 bb = *(const float4*)(b + lane * 4);
    float4 o;
    o.x = fmaxf(sf.x + acc.x * inv + bb.x, 0.f);
    o.y = fmaxf(sf.y + acc.y * inv + bb.y, 0.f);
    o.z = fmaxf(sf.z + acc.z * inv + bb.z, 0.f);
    o.w = fmaxf(sf.w + acc.w * inv + bb.w, 0.f);
    store_h4(qout, (size_t)v * FDIM + lane * 4, o);
}

__global__ void k_agg_gcn128(const __half* __restrict__ qin,
                             const float* __restrict__ b,
                             __half* __restrict__ qout, int n) {
    int v = (blockIdx.x * blockDim.x + threadIdx.x) >> 5;
    int lane = threadIdx.x & 31;
    if (v >= n) { cudaGridDependencySynchronize(); return; }
    int dt = g_cnt[v];
    cudaGridDependencySynchronize();
    float4 acc = gather_sum(qin, v, lane, dt);
    float4 sf = h4_to_f4(*(const uint2*)(qin + (size_t)v * FDIM + lane * 4));
    acc4(acc, sf);
    float inv = 1.0f / ((float)dt + 1.0f);
    float4 bb = *(const float4*)(b + lane * 4);
    float4 o;
    o.x = fmaxf(acc.x * inv + bb.x, 0.f);
    o.y = fmaxf(acc.y * inv + bb.y, 0.f);
    o.z = fmaxf(acc.z * inv + bb.z, 0.f);
    o.w = fmaxf(acc.w * inv + bb.w, 0.f);
    store_h4(qout, (size_t)v * FDIM + lane * 4, o);
}

__global__ void k_agg_mean32(const float* __restrict__ t,
                             const float* __restrict__ b,
                             float* __restrict__ out, int n) {
    int v = (blockIdx.x * blockDim.x + threadIdx.x) >> 5;
    int lane = threadIdx.x & 31;
    if (v >= n) { cudaGridDependencySynchronize(); return; }
    int dt = g_cnt[v];
    cudaGridDependencySynchronize();
    int L = dt < CAP ? dt : CAP;
    const int* cp = g_col + v * CAP;
    float acc = 0.f;
    int j = 0;
    for (; j + 4 <= L; j += 4) {
        int4 u = *(const int4*)(cp + j);
        float a0 = t[(size_t)u.x * 64 + 32 + lane];
        float a1 = t[(size_t)u.y * 64 + 32 + lane];
        float a2 = t[(size_t)u.z * 64 + 32 + lane];
        float a3 = t[(size_t)u.w * 64 + 32 + lane];
        acc += a0 + a1 + a2 + a3;
    }
    for (; j < L; j++) acc += t[(size_t)cp[j] * 64 + 32 + lane];
    float inv = 1.0f / fmaxf((float)dt, 1.0f);
    out[(size_t)v * OUTF + lane] = t[(size_t)v * 64 + lane] + acc * inv + b[lane];
}

// ---------------------------------------------------------------------------
extern "C" void kernel_launch(void* const* d_in, const int* in_sizes, int n_in,
                              void* d_out, int out_size) {
    const float* x       = (const float*)d_in[0];
    const void*  src     = d_in[1];
    const void*  dst     = d_in[2];
    const float* Wself0  = (const float*)d_in[3];
    const float* Wneigh0 = (const float*)d_in[4];
    const float* b0      = (const float*)d_in[5];
    const float* Wneigh1 = (const float*)d_in[6];
    const float* b1      = (const float*)d_in[7];
    const float* Wneigh2 = (const float*)d_in[8];
    const float* b2      = (const float*)d_in[9];
    const float* Wself3  = (const float*)d_in[10];
    const float* Wneigh3 = (const float*)d_in[11];
    const float* b3      = (const float*)d_in[12];
    float* out = (float*)d_out;

    int n = in_sizes[0] / FDIM;
    int e = in_sizes[1];

    __half *wh, *wl, *qa, *qb;
    float* t0;
    int* is64p;
    cudaGetSymbolAddress((void**)&wh, g_wh);
    cudaGetSymbolAddress((void**)&wl, g_wl);
    cudaGetSymbolAddress((void**)&qa, g_qa);
    cudaGetSymbolAddress((void**)&qb, g_qb);
    cudaGetSymbolAddress((void**)&t0, g_t0);
    cudaGetSymbolAddress((void**)&is64p, g_is64);

    static cudaStream_t s1 = nullptr, s2 = nullptr;
    static cudaEvent_t eFork = nullptr, eCSR = nullptr, eW = nullptr,
                       eN = nullptr, eG1 = nullptr;
    if (!s1) {
        cudaStreamCreateWithFlags(&s1, cudaStreamNonBlocking);
        cudaStreamCreateWithFlags(&s2, cudaStreamNonBlocking);
        cudaEventCreateWithFlags(&eFork, cudaEventDisableTiming);
        cudaEventCreateWithFlags(&eCSR,  cudaEventDisableTiming);
        cudaEventCreateWithFlags(&eW,    cudaEventDisableTiming);
        cudaEventCreateWithFlags(&eN,    cudaEventDisableTiming);
        cudaEventCreateWithFlags(&eG1,   cudaEventDisableTiming);
    }

    int aggBlocks = (n + 7) / 8;
    int gemmBlocks = (n + 127) / 128;

    // PDL launch helper (stream 0, 256 threads, PSS attribute)
    cudaLaunchAttribute pdl;
    pdl.id = cudaLaunchAttributeProgrammaticStreamSerialization;
    pdl.val.programmaticStreamSerializationAllowed = 1;
    auto pdlLaunch = [&](auto kern, int grid, auto... args) {
        cudaLaunchConfig_t c = {};
        c.gridDim = dim3(grid);
        c.blockDim = dim3(256);
        c.stream = 0;
        c.attrs = &pdl;
        c.numAttrs = 1;
        cudaLaunchKernelEx(&c, kern, args...);
    };

    // fork
    cudaMemsetAsync(is64p, 1, 4);               // nonzero => int64 until refuted
    cudaEventRecord(eFork, 0);

    // s1: CSR build
    cudaStreamWaitEvent(s1, eFork, 0);
    k_zero_detect<<<1024, 256, 0, s1>>>((const int*)dst, n, e);
    k_scatter<<<1024, 256, 0, s1>>>(src, dst, e);
    cudaEventRecord(eCSR, s1);

    // s2: weight split
    cudaStreamWaitEvent(s2, eFork, 0);
    k_wsplit<<<(73728 + 255) / 256, 256, 0, s2>>>(Wself0, Wneigh0, Wneigh1,
                                                  Wneigh2, Wself3, Wneigh3);
    cudaEventRecord(eW, s2);

    // s0: norm -> qa (fp16)
    k_norm<<<aggBlocks, 256>>>(x, qa, n);
    cudaEventRecord(eN, 0);

    // s0: L0 self GEMM qa -> t0 (fp32), PDL vs norm
    cudaStreamWaitEvent(0, eW, 0);
    pdlLaunch(k_gemm_h<128, false>, gemmBlocks,
              (const __half*)qa, (const __half*)wh, (const __half*)wl,
              t0, qb, n);

    // s2: L0 neigh GEMM qa -> qb (fp16), normal launch (same-stream pred is
    // wsplit, which produces the weights read in the pre-sync prologue)
    cudaStreamWaitEvent(s2, eN, 0);
    k_gemm_h<128, true><<<gemmBlocks, 256, 0, s2>>>(qa, wh + 16384, wl + 16384,
                                                    t0, qb, n);
    cudaEventRecord(eG1, s2);

    // s0: join, then PDL-chained serial tail (ping-pong qa/qb)
    cudaStreamWaitEvent(0, eCSR, 0);
    cudaStreamWaitEvent(0, eG1, 0);
    pdlLaunch(k_agg_mean128, aggBlocks,
              (const float*)t0, (const __half*)qb, b0, qa, n);

    pdlLaunch(k_gemm_h<128, true>, gemmBlocks,
              (const __half*)qa, (const __half*)(wh + 32768),
              (const __half*)(wl + 32768), t0, qb, n);
    pdlLaunch(k_agg_gcn128, aggBlocks, (const __half*)qb, b1, qa, n);

    pdlLaunch(k_gemm_h<128, true>, gemmBlocks,
              (const __half*)qa, (const __half*)(wh + 49152),
              (const __half*)(wl + 49152), t0, qb, n);
    pdlLaunch(k_agg_gcn128, aggBlocks, (const __half*)qb, b2, qa, n);

    pdlLaunch(k_gemm_h<64, false>, gemmBlocks,
              (const __half*)qa, (const __half*)(wh + 65536),
              (const __half*)(wl + 65536), t0, qb, n);
    pdlLaunch(k_agg_mean32, aggBlocks, (const float*)t0, b3, out, n);
}

// round 14
// speedup vs baseline: 1.3765x; 1.0104x over previous
#include <cuda_runtime.h>
#include <cuda_fp16.h>
#include <cstdint>

// GraphSAGE: N=50000, E=800000, 128 -> 128 -> 128 -> 32
// R12 skeleton (stable): all-fp16 activations, PDL serial tail, fork-join CSR
// + wsplit, L0 GEMM pair on parallel streams. This round adds:
//  - norm: half-warp per node (2 nodes/warp ILP)
//  - gathers: unroll 8 (MLP 8)
//  - L3 GEMM dual-output: fp32 t0[n,64] + fp16 neighbor mirror qb[n,32];
//    final aggregation gathers fp16 (64B/edge).

#define NN 50000
#define FDIM 128
#define OUTF 32
#define CAP 96

__device__ __half g_wh[73728];
__device__ __half g_wl[73728];
__device__ float  g_t0[NN * FDIM];
__device__ __half g_qa[NN * FDIM];
__device__ __half g_qb[NN * FDIM];
__device__ int    g_cnt[NN];
__device__ int    g_col[NN * CAP];
__device__ int    g_is64;

// ---------------------------------------------------------------------------
__device__ __forceinline__ void split_fp16(float v, __half& hi, __half& lo) {
    hi = __float2half_rn(v);
    lo = __float2half_rn(v - __half2float(hi));
}

__device__ __forceinline__ void store_h4(__half* q, size_t off, float4 o) {
    *(__half2*)(q + off)     = __float22half2_rn(make_float2(o.x, o.y));
    *(__half2*)(q + off + 2) = __float22half2_rn(make_float2(o.z, o.w));
}

__device__ __forceinline__ void cpa16(uint32_t dst, const void* src, int szz) {
    asm volatile("cp.async.ca.shared.global [%0], [%1], 16, %2;"
                 :: "r"(dst), "l"(src), "r"(szz));
}
#define CP_COMMIT asm volatile("cp.async.commit_group;" ::: "memory")
#define CP_WAIT1  asm volatile("cp.async.wait_group 1;" ::: "memory")
#define CP_WAIT0  asm volatile("cp.async.wait_group 0;" ::: "memory")

__device__ __forceinline__ void ldsm4(uint32_t r[4], uint32_t addr) {
    asm volatile("ldmatrix.sync.aligned.m8n8.x4.shared.b16 {%0,%1,%2,%3}, [%4];"
                 : "=r"(r[0]), "=r"(r[1]), "=r"(r[2]), "=r"(r[3]) : "r"(addr));
}
__device__ __forceinline__ void ldsm4t(uint32_t r[4], uint32_t addr) {
    asm volatile("ldmatrix.sync.aligned.m8n8.x4.trans.shared.b16 {%0,%1,%2,%3}, [%4];"
                 : "=r"(r[0]), "=r"(r[1]), "=r"(r[2]), "=r"(r[3]) : "r"(addr));
}
__device__ __forceinline__ void mma16816(float d[4], const uint32_t a[4],
                                         const uint32_t* b) {
    asm volatile(
        "mma.sync.aligned.m16n8k16.row.col.f32.f16.f16.f32 "
        "{%0,%1,%2,%3}, {%4,%5,%6,%7}, {%8,%9}, {%0,%1,%2,%3};"
        : "+f"(d[0]), "+f"(d[1]), "+f"(d[2]), "+f"(d[3])
        : "r"(a[0]), "r"(a[1]), "r"(a[2]), "r"(a[3]), "r"(b[0]), "r"(b[1]));
}

// ---------------------------------------------------------------------------
__device__ __forceinline__ int eidx(const void* p, int i, int is64) {
    return is64 ? (int)((const long long*)p)[i] : ((const int*)p)[i];
}

__global__ void k_zero_detect(const int* w, int n, int e) {
    for (int i = blockIdx.x * blockDim.x + threadIdx.x; i < e;
         i += gridDim.x * blockDim.x) {
        if (i < n) g_cnt[i] = 0;
        if ((i & 1) && w[i] != 0) g_is64 = 0;
    }
}

__global__ void k_scatter(const void* src, const void* dst, int e) {
    int is64 = g_is64;
    for (int i = blockIdx.x * blockDim.x + threadIdx.x; i < e;
         i += gridDim.x * blockDim.x) {
        int d = eidx(dst, i, is64);
        int p = atomicAdd(&g_cnt[d], 1);
        if (p < CAP) g_col[d * CAP + p] = eidx(src, i, is64);
    }
}

// ---------------------------------------------------------------------------
// Weight pre-split (fp16 hi/lo):
// [0)=Wself0 [16384)=Wneigh0 [32768)=Wneigh1 [49152)=Wneigh2
// [65536, 73728) = concat(Wself3 | Wneigh3) as [128 x 64]
// ---------------------------------------------------------------------------
__global__ void k_wsplit(const float* __restrict__ ws0, const float* __restrict__ wn0,
                         const float* __restrict__ wn1, const float* __restrict__ wn2,
                         const float* __restrict__ ws3, const float* __restrict__ wn3) {
    int i = blockIdx.x * blockDim.x + threadIdx.x;
    if (i >= 73728) return;
    float v;
    if (i < 16384) v = ws0[i];
    else if (i < 32768) v = wn0[i - 16384];
    else if (i < 49152) v = wn1[i - 32768];
    else if (i < 65536) v = wn2[i - 49152];
    else {
        int j = i - 65536, r = j >> 6, c = j & 63;
        v = (c < 32) ? ws3[r * 32 + c] : wn3[r * 32 + c - 32];
    }
    __half hi, lo;
    split_fp16(v, hi, lo);
    g_wh[i] = hi;
    g_wl[i] = lo;
}

// ---------------------------------------------------------------------------
// L2 normalize: HALF-WARP per node (2 nodes/warp, 8 floats per lane)
// ---------------------------------------------------------------------------
__global__ void k_norm(const float* __restrict__ x, __half* __restrict__ q, int n) {
    int hw = (blockIdx.x * blockDim.x + threadIdx.x) >> 4;
    int l = threadIdx.x & 15;
    if (hw >= n) return;
    size_t base = (size_t)hw * FDIM + l * 8;
    float4 a = *(const float4*)(x + base);
    float4 b = *(const float4*)(x + base + 4);
    float ss = a.x * a.x + a.y * a.y + a.z * a.z + a.w * a.w +
               b.x * b.x + b.y * b.y + b.z * b.z + b.w * b.w;
    #pragma unroll
    for (int o = 8; o; o >>= 1) ss += __shfl_xor_sync(0xFFFFFFFFu, ss, o, 16);
    float s = 1.0f / fmaxf(sqrtf(ss), 1e-12f);
    uint4 pk;
    ((__half2*)&pk)[0] = __float22half2_rn(make_float2(a.x * s, a.y * s));
    ((__half2*)&pk)[1] = __float22half2_rn(make_float2(a.z * s, a.w * s));
    ((__half2*)&pk)[2] = __float22half2_rn(make_float2(b.x * s, b.y * s));
    ((__half2*)&pk)[3] = __float22half2_rn(make_float2(b.z * s, b.w * s));
    *(uint4*)(q + base) = pk;
}

// ---------------------------------------------------------------------------
// fp16 tensor GEMM with PDL. OUTMODE: 0 = fp32 C[n,M]; 1 = fp16 Q[n,M];
// 2 = (M=64) fp32 C[n,64] + fp16 mirror of cols>=32 into Q[n,32].
// ---------------------------------------------------------------------------
template <int M>
__device__ __forceinline__ void stage_w(uint32_t dWh, uint32_t dWl,
                                        const __half* __restrict__ Wgh,
                                        const __half* __restrict__ Wgl,
                                        int k0, int tid) {
    constexpr int CW = M / 8;
    #pragma unroll
    for (int i = tid; i < 2 * 16 * CW; i += 256) {
        int half_ = i / (16 * CW), rem = i % (16 * CW);
        int r = rem / CW, seg = rem % CW;
        size_t so = (size_t)(k0 + r) * M + seg * 8;
        uint32_t dof = (uint32_t)(r * (M + 8) + seg * 8) * 2;
        if (half_ == 0) cpa16(dWh + dof, Wgh + so, 16);
        else            cpa16(dWl + dof, Wgl + so, 16);
    }
}

__device__ __forceinline__ void stage_a(uint32_t dA, const __half* __restrict__ Ag,
                                        int row0, int k0, int n, int tid) {
    int r = tid >> 1, seg = tid & 1;
    int row = row0 + r;
    int ok = (row < n) ? 16 : 0;
    size_t so = (size_t)(ok ? row : 0) * 128 + k0 + seg * 8;
    uint32_t dof = (uint32_t)(r * 24 + seg * 8) * 2;
    cpa16(dA + dof, Ag + so, ok);
}

template <int M, int OUTMODE>
__global__ void __launch_bounds__(256) k_gemm_h(
    const __half* __restrict__ Ag,
    const __half* __restrict__ Wgh, const __half* __restrict__ Wgl,
    float* __restrict__ C, __half* __restrict__ Q, int n) {
    constexpr int LDA = 24;
    constexpr int LDB = M + 8;
    constexpr int NT  = M / 16;
    __shared__ __half A[2][128 * LDA];
    __shared__ __half Wh[2][16 * LDB], Wl[2][16 * LDB];

    int tid = threadIdx.x;
    int lane = tid & 31, wid = tid >> 5;
    int row0 = blockIdx.x * 128;

    float acc[NT][2][4];
    #pragma unroll
    for (int t = 0; t < NT; t++)
        #pragma unroll
        for (int s = 0; s < 2; s++)
            #pragma unroll
            for (int c = 0; c < 4; c++) acc[t][s][c] = 0.f;

    uint32_t sA[2]  = {(uint32_t)__cvta_generic_to_shared(A[0]),
                       (uint32_t)__cvta_generic_to_shared(A[1])};
    uint32_t sWh[2] = {(uint32_t)__cvta_generic_to_shared(Wh[0]),
                       (uint32_t)__cvta_generic_to_shared(Wh[1])};
    uint32_t sWl[2] = {(uint32_t)__cvta_generic_to_shared(Wl[0]),
                       (uint32_t)__cvta_generic_to_shared(Wl[1])};

    // prologue (independent of predecessor): W chunk 0
    stage_w<M>(sWh[0], sWl[0], Wgh, Wgl, 0, tid);
    CP_COMMIT;

    cudaGridDependencySynchronize();   // predecessor produced A

    stage_a(sA[0], Ag, row0, 0, n, tid);
    CP_COMMIT;

    #pragma unroll
    for (int c = 0; c < 8; c++) {
        int b = c & 1;
        if (c < 7) {
            int nb = (c + 1) & 1;
            stage_w<M>(sWh[nb], sWl[nb], Wgh, Wgl, (c + 1) * 16, tid);
            stage_a(sA[nb], Ag, row0, (c + 1) * 16, n, tid);
            CP_COMMIT;
            CP_WAIT1;
        } else {
            CP_WAIT0;
        }
        __syncthreads();

        uint32_t aoff = ((wid * 16 + (lane & 15)) * LDA + (lane >> 4) * 8) * 2;
        uint32_t a[4];
        ldsm4(a, sA[b] + aoff);
        #pragma unroll
        for (int nt = 0; nt < NT; nt++) {
            uint32_t boff = ((lane & 15) * LDB + nt * 16 + (lane >> 4) * 8) * 2;
            uint32_t bh[4], bl[4];
            ldsm4t(bh, sWh[b] + boff);
            ldsm4t(bl, sWl[b] + boff);
            mma16816(acc[nt][0], a, bh + 0);
            mma16816(acc[nt][1], a, bh + 2);
            mma16816(acc[nt][0], a, bl + 0);
            mma16816(acc[nt][1], a, bl + 2);
        }
        __syncthreads();
    }

    int g = lane >> 2, tg = lane & 3;
    int r0 = row0 + wid * 16 + g;
    #pragma unroll
    for (int nt = 0; nt < NT; nt++) {
        #pragma unroll
        for (int s = 0; s < 2; s++) {
            int col = nt * 16 + s * 8 + tg * 2;
            float2 v01 = make_float2(acc[nt][s][0], acc[nt][s][1]);
            float2 v23 = make_float2(acc[nt][s][2], acc[nt][s][3]);
            #pragma unroll
            for (int rr = 0; rr < 2; rr++) {
                int r = r0 + rr * 8;
                float2 v = rr ? v23 : v01;
                if (r >= n) continue;
                if (OUTMODE == 0) {
                    *(float2*)(C + (size_t)r * M + col) = v;
                } else if (OUTMODE == 1) {
                    *(__half2*)(Q + (size_t)r * M + col) = __float22half2_rn(v);
                } else {  // OUTMODE 2 (M=64): fp32 + fp16 mirror of cols>=32
                    *(float2*)(C + (size_t)r * 64 + col) = v;
                    if (col >= 32)
                        *(__half2*)(Q + (size_t)r * 32 + col - 32) =
                            __float22half2_rn(v);
                }
            }
        }
    }
}

// ---------------------------------------------------------------------------
// Aggregations: warp per node, bucket CSR, unroll-8 fp16 gathers.
// PDL: CSR count read before grid-dependency sync; gathers/writes after.
// ---------------------------------------------------------------------------
__device__ __forceinline__ float4 h4_to_f4(uint2 raw) {
    __half2 p0 = *(__half2*)&raw.x;
    __half2 p1 = *(__half2*)&raw.y;
    float2 f0 = __half22float2(p0), f1 = __half22float2(p1);
    return make_float4(f0.x, f0.y, f1.x, f1.y);
}
__device__ __forceinline__ void acc4(float4& a, float4 t) {
    a.x += t.x; a.y += t.y; a.z += t.z; a.w += t.w;
}

__device__ __forceinline__ float4 gather_sum(const __half* __restrict__ q,
                                             int v, int lane, int dt) {
    int L = dt < CAP ? dt : CAP;
    const int* cp = g_col + v * CAP;
    float4 acc = make_float4(0.f, 0.f, 0.f, 0.f);
    int j = 0;
    for (; j + 8 <= L; j += 8) {
        int4 u0 = *(const int4*)(cp + j);
        int4 u1 = *(const int4*)(cp + j + 4);
        uint2 a0 = *(const uint2*)(q + (size_t)u0.x * FDIM + lane * 4);
        uint2 a1 = *(const uint2*)(q + (size_t)u0.y * FDIM + lane * 4);
        uint2 a2 = *(const uint2*)(q + (size_t)u0.z * FDIM + lane * 4);
        uint2 a3 = *(const uint2*)(q + (size_t)u0.w * FDIM + lane * 4);
        uint2 a4 = *(const uint2*)(q + (size_t)u1.x * FDIM + lane * 4);
        uint2 a5 = *(const uint2*)(q + (size_t)u1.y * FDIM + lane * 4);
        uint2 a6 = *(const uint2*)(q + (size_t)u1.z * FDIM + lane * 4);
        uint2 a7 = *(const uint2*)(q + (size_t)u1.w * FDIM + lane * 4);
        acc4(acc, h4_to_f4(a0)); acc4(acc, h4_to_f4(a1));
        acc4(acc, h4_to_f4(a2)); acc4(acc, h4_to_f4(a3));
        acc4(acc, h4_to_f4(a4)); acc4(acc, h4_to_f4(a5));
        acc4(acc, h4_to_f4(a6)); acc4(acc, h4_to_f4(a7));
    }
    for (; j + 4 <= L; j += 4) {
        int4 u = *(const int4*)(cp + j);
        uint2 a0 = *(const uint2*)(q + (size_t)u.x * FDIM + lane * 4);
        uint2 a1 = *(const uint2*)(q + (size_t)u.y * FDIM + lane * 4);
        uint2 a2 = *(const uint2*)(q + (size_t)u.z * FDIM + lane * 4);
        uint2 a3 = *(const uint2*)(q + (size_t)u.w * FDIM + lane * 4);
        acc4(acc, h4_to_f4(a0)); acc4(acc, h4_to_f4(a1));
        acc4(acc, h4_to_f4(a2)); acc4(acc, h4_to_f4(a3));
    }
    for (; j < L; j++) {
        int u = cp[j];
        acc4(acc, h4_to_f4(*(const uint2*)(q + (size_t)u * FDIM + lane * 4)));
    }
    return acc;
}

__global__ void k_agg_mean128(const float* __restrict__ tself,
                              const __half* __restrict__ qnbr,
                              const float* __restrict__ b,
                              __half* __restrict__ qout, int n) {
    int v = (blockIdx.x * blockDim.x + threadIdx.x) >> 5;
    int lane = threadIdx.x & 31;
    if (v >= n) { cudaGridDependencySynchronize(); return; }
    int dt = g_cnt[v];                 // CSR ready (event-gated)
    cudaGridDependencySynchronize();
    float4 acc = gather_sum(qnbr, v, lane, dt);
    float inv = 1.0f / fmaxf((float)dt, 1.0f);
    float4 sf = *(const float4*)(tself + (size_t)v * FDIM + lane * 4);
    float4 bb = *(const float4*)(b + lane * 4);
    float4 o;
    o.x = fmaxf(sf.x + acc.x * inv + bb.x, 0.f);
    o.y = fmaxf(sf.y + acc.y * inv + bb.y, 0.f);
    o.z = fmaxf(sf.z + acc.z * inv + bb.z, 0.f);
    o.w = fmaxf(sf.w + acc.w * inv + bb.w, 0.f);
    store_h4(qout, (size_t)v * FDIM + lane * 4, o);
}

__global__ void k_agg_gcn128(const __half* __restrict__ qin,
                             const float* __restrict__ b,
                             __half* __restrict__ qout, int n) {
    int v = (blockIdx.x * blockDim.x + threadIdx.x) >> 5;
    int lane = threadIdx.x & 31;
    if (v >= n) { cudaGridDependencySynchronize(); return; }
    int dt = g_cnt[v];
    cudaGridDependencySynchronize();
    float4 acc = gather_sum(qin, v, lane, dt);
    float4 sf = h4_to_f4(*(const uint2*)(qin + (size_t)v * FDIM + lane * 4));
    acc4(acc, sf);
    float inv = 1.0f / ((float)dt + 1.0f);
    float4 bb = *(const float4*)(b + lane * 4);
    float4 o;
    o.x = fmaxf(acc.x * inv + bb.x, 0.f);
    o.y = fmaxf(acc.y * inv + bb.y, 0.f);
    o.z = fmaxf(acc.z * inv + bb.z, 0.f);
    o.w = fmaxf(acc.w * inv + bb.w, 0.f);
    store_h4(qout, (size_t)v * FDIM + lane * 4, o);
}

// layer3: self fp32 from t[n,64] cols 0-31; neighbors fp16 from qn[n,32]
__global__ void k_agg_mean32(const float* __restrict__ t,
                             const __half* __restrict__ qn,
                             const float* __restrict__ b,
                             float* __restrict__ out, int n) {
    int v = (blockIdx.x * blockDim.x + threadIdx.x) >> 5;
    int lane = threadIdx.x & 31;
    if (v >= n) { cudaGridDependencySynchronize(); return; }
    int dt = g_cnt[v];
    cudaGridDependencySynchronize();
    int L = dt < CAP ? dt : CAP;
    const int* cp = g_col + v * CAP;
    float acc = 0.f;
    int j = 0;
    for (; j + 8 <= L; j += 8) {
        int4 u0 = *(const int4*)(cp + j);
        int4 u1 = *(const int4*)(cp + j + 4);
        float a0 = __half2float(qn[(size_t)u0.x * 32 + lane]);
        float a1 = __half2float(qn[(size_t)u0.y * 32 + lane]);
        float a2 = __half2float(qn[(size_t)u0.z * 32 + lane]);
        float a3 = __half2float(qn[(size_t)u0.w * 32 + lane]);
        float a4 = __half2float(qn[(size_t)u1.x * 32 + lane]);
        float a5 = __half2float(qn[(size_t)u1.y * 32 + lane]);
        float a6 = __half2float(qn[(size_t)u1.z * 32 + lane]);
        float a7 = __half2float(qn[(size_t)u1.w * 32 + lane]);
        acc += a0 + a1 + a2 + a3 + a4 + a5 + a6 + a7;
    }
    for (; j < L; j++)
        acc += __half2float(qn[(size_t)cp[j] * 32 + lane]);
    float inv = 1.0f / fmaxf((float)dt, 1.0f);
    out[(size_t)v * OUTF + lane] = t[(size_t)v * 64 + lane] + acc * inv + b[lane];
}

// ---------------------------------------------------------------------------
extern "C" void kernel_launch(void* const* d_in, const int* in_sizes, int n_in,
                              void* d_out, int out_size) {
    const float* x       = (const float*)d_in[0];
    const void*  src     = d_in[1];
    const void*  dst     = d_in[2];
    const float* Wself0  = (const float*)d_in[3];
    const float* Wneigh0 = (const float*)d_in[4];
    const float* b0      = (const float*)d_in[5];
    const float* Wneigh1 = (const float*)d_in[6];
    const float* b1      = (const float*)d_in[7];
    const float* Wneigh2 = (const float*)d_in[8];
    const float* b2      = (const float*)d_in[9];
    const float* Wself3  = (const float*)d_in[10];
    const float* Wneigh3 = (const float*)d_in[11];
    const float* b3      = (const float*)d_in[12];
    float* out = (float*)d_out;

    int n = in_sizes[0] / FDIM;
    int e = in_sizes[1];

    __half *wh, *wl, *qa, *qb;
    float* t0;
    int* is64p;
    cudaGetSymbolAddress((void**)&wh, g_wh);
    cudaGetSymbolAddress((void**)&wl, g_wl);
    cudaGetSymbolAddress((void**)&qa, g_qa);
    cudaGetSymbolAddress((void**)&qb, g_qb);
    cudaGetSymbolAddress((void**)&t0, g_t0);
    cudaGetSymbolAddress((void**)&is64p, g_is64);

    static cudaStream_t s1 = nullptr, s2 = nullptr;
    static cudaEvent_t eFork = nullptr, eCSR = nullptr, eW = nullptr,
                       eN = nullptr, eG1 = nullptr;
    if (!s1) {
        cudaStreamCreateWithFlags(&s1, cudaStreamNonBlocking);
        cudaStreamCreateWithFlags(&s2, cudaStreamNonBlocking);
        cudaEventCreateWithFlags(&eFork, cudaEventDisableTiming);
        cudaEventCreateWithFlags(&eCSR,  cudaEventDisableTiming);
        cudaEventCreateWithFlags(&eW,    cudaEventDisableTiming);
        cudaEventCreateWithFlags(&eN,    cudaEventDisableTiming);
        cudaEventCreateWithFlags(&eG1,   cudaEventDisableTiming);
    }

    int aggBlocks  = (n + 7) / 8;
    int normBlocks = (n + 15) / 16;
    int gemmBlocks = (n + 127) / 128;

    // PDL launch helper
    cudaLaunchAttribute pdl;
    pdl.id = cudaLaunchAttributeProgrammaticStreamSerialization;
    pdl.val.programmaticStreamSerializationAllowed = 1;
    auto pdlLaunch = [&](auto kern, int grid, auto... args) {
        cudaLaunchConfig_t c = {};
        c.gridDim = dim3(grid);
        c.blockDim = dim3(256);
        c.stream = 0;
        c.attrs = &pdl;
        c.numAttrs = 1;
        cudaLaunchKernelEx(&c, kern, args...);
    };

    // fork
    cudaMemsetAsync(is64p, 1, 4);               // nonzero => int64 until refuted
    cudaEventRecord(eFork, 0);

    // s1: CSR build
    cudaStreamWaitEvent(s1, eFork, 0);
    k_zero_detect<<<1024, 256, 0, s1>>>((const int*)dst, n, e);
    k_scatter<<<1024, 256, 0, s1>>>(src, dst, e);
    cudaEventRecord(eCSR, s1);

    // s2: weight split
    cudaStreamWaitEvent(s2, eFork, 0);
    k_wsplit<<<(73728 + 255) / 256, 256, 0, s2>>>(Wself0, Wneigh0, Wneigh1,
                                                  Wneigh2, Wself3, Wneigh3);
    cudaEventRecord(eW, s2);

    // s0: norm -> qa (fp16)
    k_norm<<<normBlocks, 256>>>(x, qa, n);
    cudaEventRecord(eN, 0);

    // s0: L0 self GEMM qa -> t0 (fp32), PDL vs norm
    cudaStreamWaitEvent(0, eW, 0);
    pdlLaunch(k_gemm_h<128, 0>, gemmBlocks,
              (const __half*)qa, (const __half*)wh, (const __half*)wl,
              t0, qb, n);

    // s2: L0 neigh GEMM qa -> qb (fp16), normal launch
    cudaStreamWaitEvent(s2, eN, 0);
    k_gemm_h<128, 1><<<gemmBlocks, 256, 0, s2>>>(qa, wh + 16384, wl + 16384,
                                                 t0, qb, n);
    cudaEventRecord(eG1, s2);

    // s0: join, PDL-chained serial tail (ping-pong qa/qb)
    cudaStreamWaitEvent(0, eCSR, 0);
    cudaStreamWaitEvent(0, eG1, 0);
    pdlLaunch(k_agg_mean128, aggBlocks,
              (const float*)t0, (const __half*)qb, b0, qa, n);

    pdlLaunch(k_gemm_h<128, 1>, gemmBlocks,
              (const __half*)qa, (const __half*)(wh + 32768),
              (const __half*)(wl + 32768), t0, qb, n);
    pdlLaunch(k_agg_gcn128, aggBlocks, (const __half*)qb, b1, qa, n);

    pdlLaunch(k_gemm_h<128, 1>, gemmBlocks,
              (const __half*)qa, (const __half*)(wh + 49152),
              (const __half*)(wl + 49152), t0, qb, n);
    pdlLaunch(k_agg_gcn128, aggBlocks, (const __half*)qb, b2, qa, n);

    // L3: dual-output GEMM -> t0[n,64] fp32 + qb[n,32] fp16 neighbor mirror
    pdlLaunch(k_gemm_h<64, 2>, gemmBlocks,
              (const __half*)qa, (const __half*)(wh + 65536),
              (const __half*)(wl + 65536), t0, qb, n);
    pdlLaunch(k_agg_mean32, aggBlocks,
              (const float*)t0, (const __half*)qb, b3, out, n);
}